// round 6
// baseline (speedup 1.0000x reference)
#include <cuda_runtime.h>
#include <cuda_fp16.h>
#include <math.h>
#include <stdint.h>

#define D    1024
#define DFF  4096
#define E    8
#define TOK  8192
#define BM   128
#define BN   128
#define BKI  64              // int8 k per chunk (2 IMMA k-steps)
#define STAGES 3
#define ROWB 192             // 128B data (2 ksteps x 4 groups x 16B) + 64B pad
#define ABLK (BM*ROWB)       // 24576
#define STGB (2*ABLK)        // 49152 (A + B, both 128 rows)
#define SMEM_BYTES (STAGES*STGB)   // 147456
#define MAXROWS (2*TOK + E*BM)     // 17408
#define NROWT (MAXROWS/BM)         // 136
#define QMAX 16256.0f

// ---------------- scratch ----------------
__device__ int   g_eid[TOK*2];
__device__ float g_gw[TOK*2];
__device__ int   g_counts[E];
__device__ int   g_off[E+1];
__device__ int   g_cursor[E];
__device__ int   g_total;
__device__ int   g_slot_token[MAXROWS];
__device__ int   g_slot_of[TOK*2];
__device__ float g_usage[E];
// quantized operands: per row 2 bytes/elem (hi+lo planes interleaved in 16B groups)
__device__ uint8_t g_xq[(size_t)TOK*2048];          // [token][D packed]
__device__ float   g_sx[TOK];
__device__ uint8_t g_w1q[(size_t)E*DFF*2048];       // [e*DFF + f][D packed]
__device__ uint8_t g_w2q[(size_t)E*D*8192];         // [e*D + d][DFF packed]
__device__ float   g_sw1[E*DFF], g_iw1[E*DFF], g_w1max[E*DFF];
__device__ float   g_sw2[E*D],   g_iw2[E*D],   g_w2max[E*D];
__device__ float   g_hf[(size_t)MAXROWS*DFF];       // fp32 h between GEMMs
__device__ uint8_t g_hq[(size_t)MAXROWS*8192];      // [row][DFF packed]
__device__ float   g_sh[MAXROWS];
__device__ float   g_y[(size_t)MAXROWS*D];

// ---------------- helpers ----------------
__device__ __forceinline__ uint32_t smem_u32(const void* p) {
    uint32_t a;
    asm("{ .reg .u64 t; cvta.to.shared.u64 t, %1; cvt.u32.u64 %0, t; }" : "=r"(a) : "l"(p));
    return a;
}
#define CPA(dst, src) asm volatile("cp.async.cg.shared.global [%0], [%1], 16;" :: "r"(dst), "l"(src) : "memory")
#define CPCOMMIT()    asm volatile("cp.async.commit_group;" ::: "memory")
#define CPWAIT(n)     asm volatile("cp.async.wait_group %0;" :: "n"(n) : "memory")
#define IMMA(c, a, b) asm volatile( \
    "mma.sync.aligned.m16n8k32.row.col.s32.s8.s8.s32 " \
    "{%0,%1,%2,%3},{%4,%5,%6,%7},{%8,%9},{%0,%1,%2,%3};" \
    : "+r"((c)[0]),"+r"((c)[1]),"+r"((c)[2]),"+r"((c)[3]) \
    : "r"((a)[0]),"r"((a)[1]),"r"((a)[2]),"r"((a)[3]),"r"((b)[0]),"r"((b)[1]))

// quantize 8 floats (4 at k, 4 at k+16) into one 16B group {hi0,hi1,lo0,lo1}
__device__ __forceinline__ uint4 quant8(float4 a, float4 b, float inv) {
    float va[4] = {a.x, a.y, a.z, a.w};
    float vb[4] = {b.x, b.y, b.z, b.w};
    uint32_t h0 = 0, h1 = 0, l0 = 0, l1 = 0;
    #pragma unroll
    for (int i = 0; i < 4; i++) {
        int X  = __float2int_rn(va[i] * inv);
        int X1 = (X + 64) >> 7;
        int X0 = X - (X1 << 7);
        h0 |= (uint32_t)(uint8_t)X1 << (8*i);
        l0 |= (uint32_t)(uint8_t)X0 << (8*i);
        X  = __float2int_rn(vb[i] * inv);
        X1 = (X + 64) >> 7;
        X0 = X - (X1 << 7);
        h1 |= (uint32_t)(uint8_t)X1 << (8*i);
        l1 |= (uint32_t)(uint8_t)X0 << (8*i);
    }
    return make_uint4(h0, h1, l0, l1);
}

// ---------------- init ----------------
__global__ void k_init() {
    int i = blockIdx.x*blockDim.x + threadIdx.x;
    if (i < MAXROWS) g_slot_token[i] = 0;
    if (i < E) { g_counts[i] = 0; g_usage[i] = 0.f; }
    if (i < E*DFF) g_w1max[i] = 0.f;
    if (i < E*D)   g_w2max[i] = 0.f;
}

// ---------------- gating ----------------
__global__ __launch_bounds__(256) void k_gate(const float* __restrict__ x,
                                              const float* __restrict__ Wg) {
    __shared__ float sWg[E*D];
    for (int i = threadIdx.x; i < E*D; i += blockDim.x) sWg[i] = Wg[i];
    __syncthreads();
    int warp = threadIdx.x >> 5, lane = threadIdx.x & 31;
    int t = blockIdx.x * 8 + warp;
    if (t >= TOK) return;
    const float* xr = x + (size_t)t * D;
    float acc[E];
    #pragma unroll
    for (int e = 0; e < E; e++) acc[e] = 0.f;
    for (int d = lane; d < D; d += 32) {
        float xv = xr[d];
        #pragma unroll
        for (int e = 0; e < E; e++) acc[e] += xv * sWg[e*D + d];
    }
    #pragma unroll
    for (int e = 0; e < E; e++)
        #pragma unroll
        for (int o = 16; o > 0; o >>= 1)
            acc[e] += __shfl_xor_sync(0xffffffffu, acc[e], o);
    if (lane == 0) {
        int i0 = 0; float v0 = acc[0];
        #pragma unroll
        for (int e = 1; e < E; e++) if (acc[e] > v0) { v0 = acc[e]; i0 = e; }
        int i1 = -1; float v1 = -INFINITY;
        #pragma unroll
        for (int e = 0; e < E; e++) if (e != i0 && acc[e] > v1) { v1 = acc[e]; i1 = e; }
        float ex = expf(v1 - v0);
        float inv = 1.f / (1.f + ex);
        g_eid[t*2] = i0; g_eid[t*2+1] = i1;
        g_gw[t*2]  = inv; g_gw[t*2+1] = ex * inv;
        atomicAdd(&g_counts[i0], 1); atomicAdd(&g_counts[i1], 1);
        atomicAdd(&g_usage[i0], inv); atomicAdd(&g_usage[i1], ex*inv);
    }
}

// ---------------- offsets + lb loss ----------------
__global__ void k_offsets(float* loss_out, int write_loss) {
    int off = 0;
    g_off[0] = 0;
    for (int e = 0; e < E; e++) {
        g_cursor[e] = off;
        off += (g_counts[e] + BM - 1) / BM * BM;
        g_off[e+1] = off;
    }
    g_total = off;
    if (write_loss) {
        float u[E]; float mean = 0.f;
        for (int e = 0; e < E; e++) { u[e] = g_usage[e] / (float)TOK; mean += u[e]; }
        mean /= (float)E;
        float var = 0.f;
        for (int e = 0; e < E; e++) { float d = u[e] - mean; var += d * d; }
        var /= (float)(E - 1);
        loss_out[0] = var * 0.01f;
    }
}

// ---------------- scatter ----------------
__global__ void k_scatter() {
    int i = blockIdx.x*blockDim.x + threadIdx.x;
    if (i >= TOK*2) return;
    int e = g_eid[i];
    int pos = atomicAdd(&g_cursor[e], 1);
    g_slot_token[pos] = i >> 1;
    g_slot_of[i] = pos;
}

// ---------------- quantize x: warp per token ----------------
__global__ __launch_bounds__(256) void k_quant_x(const float* __restrict__ x) {
    int warp = threadIdx.x >> 5, lane = threadIdx.x & 31;
    int t = blockIdx.x * 8 + warp;
    if (t >= TOK) return;
    const float* xr = x + (size_t)t * D;
    float m = 0.f;
    #pragma unroll
    for (int j = 0; j < 8; j++) {
        float4 v = ((const float4*)xr)[lane + 32*j];
        m = fmaxf(m, fmaxf(fmaxf(fabsf(v.x), fabsf(v.y)), fmaxf(fabsf(v.z), fabsf(v.w))));
    }
    #pragma unroll
    for (int o = 16; o > 0; o >>= 1) m = fmaxf(m, __shfl_xor_sync(0xffffffffu, m, o));
    float inv = m > 0.f ? QMAX/m : 0.f;
    if (lane == 0) g_sx[t] = m / QMAX;
    #pragma unroll
    for (int j = 0; j < 4; j++) {
        int grp = lane + 32*j;
        int s = grp >> 2, t4 = grp & 3;
        int k0 = 32*s + 4*t4;
        float4 va = *(const float4*)(xr + k0);
        float4 vb = *(const float4*)(xr + k0 + 16);
        *(uint4*)(g_xq + (size_t)t*2048 + s*64 + t4*16) = quant8(va, vb, inv);
    }
}

// ---------------- weight col-max (atomic partial) ----------------
__global__ void k_wmax(const float* __restrict__ W, int R, int C, int which) {
    int c = blockIdx.x*256 + threadIdx.x;
    int e = blockIdx.y;
    int r0 = blockIdx.z * (R/8), r1 = r0 + R/8;
    const float* p = W + (size_t)e*R*C + c;
    float m = 0.f;
    for (int r = r0; r < r1; r++) m = fmaxf(m, fabsf(p[(size_t)r*C]));
    float* mx = which ? g_w2max : g_w1max;
    atomicMax((int*)(mx + e*C + c), __float_as_int(m));
}

__global__ void k_wscale() {
    int i = blockIdx.x*blockDim.x + threadIdx.x;
    if (i < E*DFF) {
        float m = g_w1max[i];
        g_sw1[i] = m / QMAX;
        g_iw1[i] = m > 0.f ? QMAX/m : 0.f;
    }
    if (i < E*D) {
        float m = g_w2max[i];
        g_sw2[i] = m / QMAX;
        g_iw2[i] = m > 0.f ? QMAX/m : 0.f;
    }
}

// ---------------- transpose + quantize weights ----------------
// in: [E][R][C] fp32 -> out rows: [e*C + c][R packed int8], which: 0->W1, 1->W2
__global__ void k_wquant(const float* __restrict__ W, int R, int C, int which) {
    __shared__ float t[32][33];
    __shared__ char scr[8][64];
    int e = blockIdx.z;
    int c0 = blockIdx.x * 32, r0 = blockIdx.y * 32;
    int tx = threadIdx.x, ty = threadIdx.y;
    const float* in = W + (size_t)e * R * C;
    #pragma unroll
    for (int i = ty; i < 32; i += 8)
        t[i][tx] = in[(size_t)(r0 + i) * C + c0 + tx];
    __syncthreads();
    uint8_t* outq = which ? g_w2q : g_w1q;
    const float* iw = which ? g_iw2 : g_iw1;
    int seg = r0 >> 5;
    int t4 = (tx >> 2) & 3, khalf = tx >> 4, b = tx & 3;
    int pos = t4*16 + khalf*4 + b;
    #pragma unroll
    for (int mi = 0; mi < 4; mi++) {
        int i = ty*4 + mi;
        int orow = c0 + i;
        float inv = iw[e*C + orow];
        float v = t[tx][i];
        int X  = __float2int_rn(v * inv);
        int X1 = (X + 64) >> 7;
        int X0 = X - (X1 << 7);
        scr[ty][pos]     = (char)X1;
        scr[ty][pos + 8] = (char)X0;
        __syncwarp();
        if (tx < 4) {
            uint4 val = *(uint4*)&scr[ty][tx*16];
            *(uint4*)(outq + (size_t)(e*C + orow)*(R*2) + seg*64 + tx*16) = val;
        }
        __syncwarp();
    }
}

// ---------------- quantize h: block per slot row ----------------
__global__ __launch_bounds__(256) void k_quant_h() {
    int row = blockIdx.x;
    if (row >= g_total) return;
    const float* hr = g_hf + (size_t)row * DFF;
    __shared__ float red[8];
    __shared__ float bc;
    int tid = threadIdx.x, wid = tid >> 5, lane = tid & 31;
    float m = 0.f;
    #pragma unroll
    for (int j = 0; j < 4; j++) {
        float4 v = ((const float4*)hr)[tid + 256*j];
        m = fmaxf(m, fmaxf(fmaxf(fabsf(v.x), fabsf(v.y)), fmaxf(fabsf(v.z), fabsf(v.w))));
    }
    #pragma unroll
    for (int o = 16; o > 0; o >>= 1) m = fmaxf(m, __shfl_xor_sync(0xffffffffu, m, o));
    if (lane == 0) red[wid] = m;
    __syncthreads();
    if (tid == 0) {
        float mm = red[0];
        #pragma unroll
        for (int i = 1; i < 8; i++) mm = fmaxf(mm, red[i]);
        bc = mm;
        g_sh[row] = mm / QMAX;
    }
    __syncthreads();
    float mx = bc;
    float inv = mx > 0.f ? QMAX/mx : 0.f;
    // DFF=4096 -> 128 segments x 4 groups = 512 groups total (NOT 1024!)
    #pragma unroll
    for (int j = 0; j < 2; j++) {
        int grp = tid + 256*j;
        int s = grp >> 2, t4 = grp & 3;
        int k0 = 32*s + 4*t4;
        float4 va = *(const float4*)(hr + k0);
        float4 vb = *(const float4*)(hr + k0 + 16);
        *(uint4*)(g_hq + (size_t)row*8192 + s*64 + t4*16) = quant8(va, vb, inv);
    }
}

// ================= int8 IMMA GEMMs: CTA 128x128, warp 64x32 =================

__global__ void __launch_bounds__(256, 1) k_gemm1_i8(const float* __restrict__ b1) {
    extern __shared__ __align__(128) char smem[];
    __shared__ int stok[BM];
    __shared__ float sxs[BM];
    const int tid = threadIdx.x, wid = tid >> 5, lane = tid & 31;
    const int g = lane >> 2, t4 = lane & 3;
    const int row0 = blockIdx.y * BM;
    if (row0 >= g_total) return;
    int e = 0;
    #pragma unroll
    for (int i = 1; i < E; i++) if (row0 >= g_off[i]) e = i;
    const int n0 = blockIdx.x * BN;
    const int wm = (wid & 1) * 64, wn = (wid >> 1) * 32;

    if (tid < BM) {
        int s = g_slot_token[row0 + tid];
        stok[tid] = s;
        sxs[tid] = g_sx[s];
    }
    __syncthreads();
    const uint32_t sb = smem_u32(smem);

    #define STAGE(st, c) do { \
        uint32_t base = sb + (st)*STGB; \
        _Pragma("unroll") \
        for (int j = 0; j < 4; j++) { \
            int idx = j*256 + tid, row = idx >> 3, part = idx & 7; \
            CPA(base + row*ROWB + part*16, \
                g_xq + (size_t)stok[row]*2048 + (c)*128 + part*16); \
        } \
        _Pragma("unroll") \
        for (int j = 0; j < 4; j++) { \
            int idx = j*256 + tid, row = idx >> 3, part = idx & 7; \
            CPA(base + ABLK + row*ROWB + part*16, \
                g_w1q + (size_t)(e*DFF + n0 + row)*2048 + (c)*128 + part*16); \
        } \
    } while (0)

    const int NC = D / BKI;   // 16
    STAGE(0, 0); CPCOMMIT();
    STAGE(1, 1); CPCOMMIT();

    int acch[4][4][4] = {};
    int accm[4][4][4] = {};
    int cs = 0, ls = 2;
    for (int c = 0; c < NC; c++) {
        CPWAIT(1);
        __syncthreads();
        if (c + 2 < NC) STAGE(ls, c + 2);
        CPCOMMIT();
        const char* sp = smem + cs * STGB;
        #pragma unroll
        for (int ks = 0; ks < 2; ks++) {
            uint4 A0[4], A1[4], B0[4];
            #pragma unroll
            for (int mt = 0; mt < 4; mt++) {
                const char* p = sp + (wm + mt*16 + g)*ROWB + ks*64 + t4*16;
                A0[mt] = *(const uint4*)p;
                A1[mt] = *(const uint4*)(p + 8*ROWB);
            }
            #pragma unroll
            for (int nt = 0; nt < 4; nt++)
                B0[nt] = *(const uint4*)(sp + ABLK + (wn + nt*8 + g)*ROWB + ks*64 + t4*16);
            #pragma unroll
            for (int mt = 0; mt < 4; mt++) {
                uint32_t ah[4] = {A0[mt].x, A1[mt].x, A0[mt].y, A1[mt].y};
                uint32_t al[4] = {A0[mt].z, A1[mt].z, A0[mt].w, A1[mt].w};
                #pragma unroll
                for (int nt = 0; nt < 4; nt++) {
                    uint32_t bh[2] = {B0[nt].x, B0[nt].y};
                    uint32_t bl[2] = {B0[nt].z, B0[nt].w};
                    IMMA(acch[mt][nt], ah, bh);
                    IMMA(accm[mt][nt], ah, bl);
                    IMMA(accm[mt][nt], al, bh);
                }
            }
        }
        cs = (cs == 2) ? 0 : cs + 1;
        ls = (ls == 2) ? 0 : ls + 1;
    }

    // epilogue: combine digits + bias + exact gelu -> fp32 h
    #pragma unroll
    for (int mt = 0; mt < 4; mt++) {
        #pragma unroll
        for (int nt = 0; nt < 4; nt++) {
            int col = n0 + wn + nt*8 + t4*2;
            float sw0 = __ldg(&g_sw1[e*DFF + col]);
            float sw1 = __ldg(&g_sw1[e*DFF + col + 1]);
            float bi0 = __ldg(&b1[e*DFF + col]);
            float bi1 = __ldg(&b1[e*DFF + col + 1]);
            #pragma unroll
            for (int h = 0; h < 2; h++) {
                int r = wm + mt*16 + g + h*8;
                float sx = sxs[r];
                float v0 = sx*sw0*(16384.f*(float)acch[mt][nt][2*h]   + 128.f*(float)accm[mt][nt][2*h])   + bi0;
                float v1 = sx*sw1*(16384.f*(float)acch[mt][nt][2*h+1] + 128.f*(float)accm[mt][nt][2*h+1]) + bi1;
                float g0 = 0.5f * v0 * (1.f + erff(v0 * 0.7071067811865476f));
                float g1 = 0.5f * v1 * (1.f + erff(v1 * 0.7071067811865476f));
                *(float2*)(g_hf + (size_t)(row0 + r)*DFF + col) = make_float2(g0, g1);
            }
        }
    }
    #undef STAGE
}

__global__ void __launch_bounds__(256, 1) k_gemm2_i8(const float* __restrict__ b2) {
    extern __shared__ __align__(128) char smem[];
    __shared__ float sxs[BM];
    const int tid = threadIdx.x, wid = tid >> 5, lane = tid & 31;
    const int g = lane >> 2, t4 = lane & 3;
    const int row0 = blockIdx.y * BM;
    if (row0 >= g_total) return;
    int e = 0;
    #pragma unroll
    for (int i = 1; i < E; i++) if (row0 >= g_off[i]) e = i;
    const int n0 = blockIdx.x * BN;
    const int wm = (wid & 1) * 64, wn = (wid >> 1) * 32;

    if (tid < BM) sxs[tid] = g_sh[row0 + tid];
    __syncthreads();
    const uint32_t sb = smem_u32(smem);

    #define STAGE(st, c) do { \
        uint32_t base = sb + (st)*STGB; \
        _Pragma("unroll") \
        for (int j = 0; j < 4; j++) { \
            int idx = j*256 + tid, row = idx >> 3, part = idx & 7; \
            CPA(base + row*ROWB + part*16, \
                g_hq + (size_t)(row0 + row)*8192 + (c)*128 + part*16); \
        } \
        _Pragma("unroll") \
        for (int j = 0; j < 4; j++) { \
            int idx = j*256 + tid, row = idx >> 3, part = idx & 7; \
            CPA(base + ABLK + row*ROWB + part*16, \
                g_w2q + (size_t)(e*D + n0 + row)*8192 + (c)*128 + part*16); \
        } \
    } while (0)

    const int NC = DFF / BKI;   // 64
    STAGE(0, 0); CPCOMMIT();
    STAGE(1, 1); CPCOMMIT();

    int acch[4][4][4] = {};
    int accm[4][4][4] = {};
    int cs = 0, ls = 2;
    for (int c = 0; c < NC; c++) {
        CPWAIT(1);
        __syncthreads();
        if (c + 2 < NC) STAGE(ls, c + 2);
        CPCOMMIT();
        const char* sp = smem + cs * STGB;
        #pragma unroll
        for (int ks = 0; ks < 2; ks++) {
            uint4 A0[4], A1[4], B0[4];
            #pragma unroll
            for (int mt = 0; mt < 4; mt++) {
                const char* p = sp + (wm + mt*16 + g)*ROWB + ks*64 + t4*16;
                A0[mt] = *(const uint4*)p;
                A1[mt] = *(const uint4*)(p + 8*ROWB);
            }
            #pragma unroll
            for (int nt = 0; nt < 4; nt++)
                B0[nt] = *(const uint4*)(sp + ABLK + (wn + nt*8 + g)*ROWB + ks*64 + t4*16);
            #pragma unroll
            for (int mt = 0; mt < 4; mt++) {
                uint32_t ah[4] = {A0[mt].x, A1[mt].x, A0[mt].y, A1[mt].y};
                uint32_t al[4] = {A0[mt].z, A1[mt].z, A0[mt].w, A1[mt].w};
                #pragma unroll
                for (int nt = 0; nt < 4; nt++) {
                    uint32_t bh[2] = {B0[nt].x, B0[nt].y};
                    uint32_t bl[2] = {B0[nt].z, B0[nt].w};
                    IMMA(acch[mt][nt], ah, bh);
                    IMMA(accm[mt][nt], ah, bl);
                    IMMA(accm[mt][nt], al, bh);
                }
            }
        }
        cs = (cs == 2) ? 0 : cs + 1;
        ls = (ls == 2) ? 0 : ls + 1;
    }

    #pragma unroll
    for (int mt = 0; mt < 4; mt++) {
        #pragma unroll
        for (int nt = 0; nt < 4; nt++) {
            int col = n0 + wn + nt*8 + t4*2;
            float sw0 = __ldg(&g_sw2[e*D + col]);
            float sw1 = __ldg(&g_sw2[e*D + col + 1]);
            float bi0 = __ldg(&b2[e*D + col]);
            float bi1 = __ldg(&b2[e*D + col + 1]);
            #pragma unroll
            for (int h = 0; h < 2; h++) {
                int r = wm + mt*16 + g + h*8;
                float sx = sxs[r];
                float v0 = sx*sw0*(16384.f*(float)acch[mt][nt][2*h]   + 128.f*(float)accm[mt][nt][2*h])   + bi0;
                float v1 = sx*sw1*(16384.f*(float)acch[mt][nt][2*h+1] + 128.f*(float)accm[mt][nt][2*h+1]) + bi1;
                *(float2*)(g_y + (size_t)(row0 + r)*D + col) = make_float2(v0, v1);
            }
        }
    }
    #undef STAGE
}

// ---------------- combine ----------------
__global__ void k_combine(float* __restrict__ out) {
    int i = blockIdx.x*blockDim.x + threadIdx.x;
    if (i >= TOK*D) return;
    int t = i >> 10;
    int d = i & 1023;
    int s0 = g_slot_of[t*2], s1 = g_slot_of[t*2+1];
    out[i] = g_gw[t*2]   * g_y[(size_t)s0*D + d]
           + g_gw[t*2+1] * g_y[(size_t)s1*D + d];
}

// ---------------- launch ----------------
extern "C" void kernel_launch(void* const* d_in, const int* in_sizes, int n_in,
                              void* d_out, int out_size) {
    const float* x  = (const float*)d_in[0];
    const float* Wg = (const float*)d_in[1];
    const float* W1 = (const float*)d_in[2];
    const float* b1 = (const float*)d_in[3];
    const float* W2 = (const float*)d_in[4];
    const float* b2 = (const float*)d_in[5];
    float* out = (float*)d_out;

    cudaFuncSetAttribute(k_gemm1_i8, cudaFuncAttributeMaxDynamicSharedMemorySize, SMEM_BYTES);
    cudaFuncSetAttribute(k_gemm2_i8, cudaFuncAttributeMaxDynamicSharedMemorySize, SMEM_BYTES);

    k_init<<<(E*DFF + 255)/256, 256>>>();
    k_gate<<<TOK/8, 256>>>(x, Wg);
    k_offsets<<<1,1>>>(out + (size_t)TOK*D, (out_size > TOK*D) ? 1 : 0);
    k_scatter<<<(TOK*2 + 255)/256, 256>>>();
    k_quant_x<<<TOK/8, 256>>>(x);
    k_wmax<<<dim3(DFF/256, E, 8), 256>>>(W1, D, DFF, 0);
    k_wmax<<<dim3(D/256, E, 8), 256>>>(W2, DFF, D, 1);
    k_wscale<<<(E*DFF + 255)/256, 256>>>();
    k_wquant<<<dim3(DFF/32, D/32, E), dim3(32,8)>>>(W1, D, DFF, 0);
    k_wquant<<<dim3(D/32, DFF/32, E), dim3(32,8)>>>(W2, DFF, D, 1);
    k_gemm1_i8<<<dim3(DFF/BN, NROWT), 256, SMEM_BYTES>>>(b1);
    k_quant_h<<<MAXROWS, 256>>>();
    k_gemm2_i8<<<dim3(D/BN, NROWT), 256, SMEM_BYTES>>>(b2);
    k_combine<<<(TOK*D + 255)/256, 256>>>(out);
}

// round 7
// speedup vs baseline: 2.3047x; 2.3047x over previous
#include <cuda_runtime.h>
#include <cuda_bf16.h>
#include <math.h>
#include <stdint.h>

#define D    1024
#define DFF  4096
#define E    8
#define TOK  8192
#define BM   128             // CTA rows
#define BN   256             // CTA cols
#define BK   32              // bf16 per K chunk
#define STAGES 4
#define ROWB 144             // 64B hi + 64B lo + 16B pad
#define ABLK (BM*ROWB)       // 18432
#define BBLK (BN*ROWB)       // 36864
#define STGB (ABLK+BBLK)     // 55296
#define SMEM_BYTES (STAGES*STGB)   // 221184
#define MAXROWS (2*TOK + E*BM)     // 17408
#define NROWT (MAXROWS/BM)         // 136

// ---------------- scratch ----------------
__device__ int   g_eid[TOK*2];
__device__ float g_gw[TOK*2];
__device__ int   g_counts[E];
__device__ int   g_off[E+1];
__device__ int   g_cursor[E];
__device__ int   g_total;
__device__ int   g_slot_token[MAXROWS];
__device__ int   g_slot_of[TOK*2];
__device__ float g_usage[E];
__device__ __nv_bfloat16 g_xhi[TOK*D],  g_xlo[TOK*D];
__device__ __nv_bfloat16 g_w1hi[E*DFF*D], g_w1lo[E*DFF*D];   // [E][DFF][D]
__device__ __nv_bfloat16 g_w2hi[E*D*DFF], g_w2lo[E*D*DFF];   // [E][D][DFF]
__device__ __nv_bfloat16 g_hhi[(size_t)MAXROWS*DFF], g_hlo[(size_t)MAXROWS*DFF];
__device__ float g_y[(size_t)MAXROWS*D];

// ---------------- helpers ----------------
__device__ __forceinline__ uint32_t smem_u32(const void* p) {
    uint32_t a;
    asm("{ .reg .u64 t; cvta.to.shared.u64 t, %1; cvt.u32.u64 %0, t; }" : "=r"(a) : "l"(p));
    return a;
}
#define CPA(dst, src) asm volatile("cp.async.cg.shared.global [%0], [%1], 16;" :: "r"(dst), "l"(src) : "memory")
#define CPCOMMIT()    asm volatile("cp.async.commit_group;" ::: "memory")
#define CPWAIT(n)     asm volatile("cp.async.wait_group %0;" :: "n"(n) : "memory")
#define MMA(c, a, b) asm volatile( \
    "mma.sync.aligned.m16n8k16.row.col.f32.bf16.bf16.f32 " \
    "{%0,%1,%2,%3},{%4,%5,%6,%7},{%8,%9},{%0,%1,%2,%3};" \
    : "+f"((c)[0]),"+f"((c)[1]),"+f"((c)[2]),"+f"((c)[3]) \
    : "r"((a)[0]),"r"((a)[1]),"r"((a)[2]),"r"((a)[3]),"r"((b)[0]),"r"((b)[1]))
#define LDSM4(r, a) asm volatile( \
    "ldmatrix.sync.aligned.m8n8.x4.shared.b16 {%0,%1,%2,%3}, [%4];" \
    : "=r"((r)[0]),"=r"((r)[1]),"=r"((r)[2]),"=r"((r)[3]) : "r"(a))

// ---------------- init ----------------
__global__ void k_init() {
    int i = blockIdx.x*blockDim.x + threadIdx.x;
    if (i < MAXROWS) g_slot_token[i] = 0;
    if (i < E) { g_counts[i] = 0; g_usage[i] = 0.f; }
}

// ---------------- gating ----------------
__global__ __launch_bounds__(256) void k_gate(const float* __restrict__ x,
                                              const float* __restrict__ Wg) {
    __shared__ float sWg[E*D];
    for (int i = threadIdx.x; i < E*D; i += blockDim.x) sWg[i] = Wg[i];
    __syncthreads();
    int warp = threadIdx.x >> 5, lane = threadIdx.x & 31;
    int t = blockIdx.x * 8 + warp;
    if (t >= TOK) return;
    const float* xr = x + (size_t)t * D;
    float acc[E];
    #pragma unroll
    for (int e = 0; e < E; e++) acc[e] = 0.f;
    for (int d = lane; d < D; d += 32) {
        float xv = xr[d];
        #pragma unroll
        for (int e = 0; e < E; e++) acc[e] += xv * sWg[e*D + d];
    }
    #pragma unroll
    for (int e = 0; e < E; e++)
        #pragma unroll
        for (int o = 16; o > 0; o >>= 1)
            acc[e] += __shfl_xor_sync(0xffffffffu, acc[e], o);
    if (lane == 0) {
        int i0 = 0; float v0 = acc[0];
        #pragma unroll
        for (int e = 1; e < E; e++) if (acc[e] > v0) { v0 = acc[e]; i0 = e; }
        int i1 = -1; float v1 = -INFINITY;
        #pragma unroll
        for (int e = 0; e < E; e++) if (e != i0 && acc[e] > v1) { v1 = acc[e]; i1 = e; }
        float ex = expf(v1 - v0);
        float inv = 1.f / (1.f + ex);
        g_eid[t*2] = i0; g_eid[t*2+1] = i1;
        g_gw[t*2]  = inv; g_gw[t*2+1] = ex * inv;
        atomicAdd(&g_counts[i0], 1); atomicAdd(&g_counts[i1], 1);
        atomicAdd(&g_usage[i0], inv); atomicAdd(&g_usage[i1], ex*inv);
    }
}

// ---------------- offsets + lb loss ----------------
__global__ void k_offsets(float* loss_out, int write_loss) {
    int off = 0;
    g_off[0] = 0;
    for (int e = 0; e < E; e++) {
        g_cursor[e] = off;
        off += (g_counts[e] + BM - 1) / BM * BM;
        g_off[e+1] = off;
    }
    g_total = off;
    if (write_loss) {
        float u[E]; float mean = 0.f;
        for (int e = 0; e < E; e++) { u[e] = g_usage[e] / (float)TOK; mean += u[e]; }
        mean /= (float)E;
        float var = 0.f;
        for (int e = 0; e < E; e++) { float d = u[e] - mean; var += d * d; }
        var /= (float)(E - 1);
        loss_out[0] = var * 0.01f;
    }
}

// ---------------- scatter ----------------
__global__ void k_scatter() {
    int i = blockIdx.x*blockDim.x + threadIdx.x;
    if (i >= TOK*2) return;
    int e = g_eid[i];
    int pos = atomicAdd(&g_cursor[e], 1);
    g_slot_token[pos] = i >> 1;
    g_slot_of[i] = pos;
}

// ---------------- split x ----------------
__global__ void k_split_x(const float* __restrict__ x) {
    int i = (blockIdx.x*blockDim.x + threadIdx.x) * 4;
    if (i >= TOK*D) return;
    float4 v = *(const float4*)(x + i);
    __nv_bfloat162 h01 = __floats2bfloat162_rn(v.x, v.y);
    __nv_bfloat162 h23 = __floats2bfloat162_rn(v.z, v.w);
    float l0 = v.x - __bfloat162float(__low2bfloat16(h01));
    float l1 = v.y - __bfloat162float(__high2bfloat16(h01));
    float l2 = v.z - __bfloat162float(__low2bfloat16(h23));
    float l3 = v.w - __bfloat162float(__high2bfloat16(h23));
    __nv_bfloat162 lo01 = __floats2bfloat162_rn(l0, l1);
    __nv_bfloat162 lo23 = __floats2bfloat162_rn(l2, l3);
    uint2 ph = make_uint2(*(uint32_t*)&h01, *(uint32_t*)&h23);
    uint2 pl = make_uint2(*(uint32_t*)&lo01, *(uint32_t*)&lo23);
    *(uint2*)((char*)g_xhi + (size_t)i*2) = ph;
    *(uint2*)((char*)g_xlo + (size_t)i*2) = pl;
}

// ---------------- transpose + split weights ----------------
__global__ void k_tsplit(const float* __restrict__ W, int R, int C, int which) {
    __shared__ float t[32][33];
    int e = blockIdx.z;
    int c0 = blockIdx.x * 32, r0 = blockIdx.y * 32;
    int tx = threadIdx.x, ty = threadIdx.y;
    const float* in = W + (size_t)e * R * C;
    #pragma unroll
    for (int i = ty; i < 32; i += 8)
        t[i][tx] = in[(size_t)(r0 + i) * C + c0 + tx];
    __syncthreads();
    __nv_bfloat16* oh = which ? g_w2hi : g_w1hi;
    __nv_bfloat16* ol = which ? g_w2lo : g_w1lo;
    size_t ob = (size_t)e * C * R;
    #pragma unroll
    for (int i = ty; i < 32; i += 8) {
        float v = t[tx][i];
        size_t oi = ob + (size_t)(c0 + i) * R + r0 + tx;
        __nv_bfloat16 h = __float2bfloat16_rn(v);
        oh[oi] = h;
        ol[oi] = __float2bfloat16_rn(v - __bfloat162float(h));
    }
}

// ================= mma.sync GEMMs, 128x256 CTA tile, 64x64 warp tile, ldmatrix =================
// stage: [A 128 rows x 144B][B 256 rows x 144B]; row = 64B hi | 64B lo | 16B pad

__global__ void __launch_bounds__(256, 1) k_gemm1_mma(const float* __restrict__ b1) {
    extern __shared__ __align__(128) char smem[];
    __shared__ int stok[BM];
    const int tid = threadIdx.x, wid = tid >> 5, lane = tid & 31;
    const int g = lane >> 2, t4 = lane & 3;
    const int row0 = blockIdx.y * BM;
    if (row0 >= g_total) return;
    int e = 0;
    #pragma unroll
    for (int i = 1; i < E; i++) if (row0 >= g_off[i]) e = i;
    const int n0 = blockIdx.x * BN;
    const int wm = (wid & 1) * 64, wn = (wid >> 1) * 64;

    if (tid < BM) stok[tid] = g_slot_token[row0 + tid];
    __syncthreads();
    const uint32_t sb = smem_u32(smem);

    // ldmatrix per-lane offsets (within stage)
    const int lq = lane & 7;
    uint32_t a_off[4], b_off[4];
    #pragma unroll
    for (int mt = 0; mt < 4; mt++)
        a_off[mt] = (uint32_t)((wm + mt*16 + lq + ((lane>>3)&1)*8)*ROWB + ((lane>>4)&1)*16);
    #pragma unroll
    for (int q = 0; q < 4; q++)
        b_off[q] = (uint32_t)(ABLK + (wn + q*16 + ((lane>>4)&1)*8 + lq)*ROWB + ((lane>>3)&1)*16);

    #define STAGE(st, c) do { \
        uint32_t base = sb + (st)*STGB; \
        int k0 = (c)*BK; \
        _Pragma("unroll") \
        for (int j = 0; j < 4; j++) { \
            int cid = j*256 + tid, row = cid >> 3, grp = cid & 7; \
            const char* src = (grp < 4 ? (const char*)g_xhi : (const char*)g_xlo) \
                              + ((size_t)stok[row]*D + k0)*2 + (grp & 3)*16; \
            CPA(base + row*ROWB + grp*16, src); \
        } \
        _Pragma("unroll") \
        for (int j = 0; j < 8; j++) { \
            int cid = j*256 + tid, row = cid >> 3, grp = cid & 7; \
            const char* src = (grp < 4 ? (const char*)g_w1hi : (const char*)g_w1lo) \
                              + (((size_t)e*DFF + n0 + row)*D + k0)*2 + (grp & 3)*16; \
            CPA(base + ABLK + row*ROWB + grp*16, src); \
        } \
    } while (0)

    const int NC = D / BK;   // 32
    #pragma unroll
    for (int c = 0; c < STAGES-1; c++) { STAGE(c, c); CPCOMMIT(); }

    float acc[4][8][4] = {};
    for (int c = 0; c < NC; c++) {
        CPWAIT(STAGES-2);
        __syncthreads();
        if (c + STAGES-1 < NC) STAGE((c + STAGES-1) & (STAGES-1), c + STAGES-1);
        CPCOMMIT();
        const uint32_t sbase = sb + (c & (STAGES-1)) * STGB;
        #pragma unroll
        for (int ks = 0; ks < 2; ks++) {
            uint32_t ah[4][4], al[4][4];
            #pragma unroll
            for (int mt = 0; mt < 4; mt++) {
                LDSM4(ah[mt], sbase + a_off[mt] + ks*32);
                LDSM4(al[mt], sbase + a_off[mt] + ks*32 + 64);
            }
            #pragma unroll
            for (int h = 0; h < 2; h++) {
                uint32_t bhq[2][4], blq[2][4];
                #pragma unroll
                for (int qq = 0; qq < 2; qq++) {
                    int q = h*2 + qq;
                    LDSM4(bhq[qq], sbase + b_off[q] + ks*32);
                    LDSM4(blq[qq], sbase + b_off[q] + ks*32 + 64);
                }
                #pragma unroll
                for (int mt = 0; mt < 4; mt++)
                    #pragma unroll
                    for (int nt = 0; nt < 4; nt++) {
                        uint32_t* bh = &bhq[nt>>1][(nt&1)*2];
                        uint32_t* bl = &blq[nt>>1][(nt&1)*2];
                        MMA(acc[mt][h*4+nt], ah[mt], bh);
                        MMA(acc[mt][h*4+nt], ah[mt], bl);
                        MMA(acc[mt][h*4+nt], al[mt], bh);
                    }
            }
        }
    }

    // epilogue: bias + exact gelu + bf16 split store
    #pragma unroll
    for (int mt = 0; mt < 4; mt++) {
        #pragma unroll
        for (int nt = 0; nt < 8; nt++) {
            int col = n0 + wn + nt*8 + t4*2;
            float bi0 = __ldg(&b1[e*DFF + col]);
            float bi1 = __ldg(&b1[e*DFF + col + 1]);
            #pragma unroll
            for (int h = 0; h < 2; h++) {
                int row = row0 + wm + mt*16 + g + h*8;
                float v0 = acc[mt][nt][2*h]   + bi0;
                float v1 = acc[mt][nt][2*h+1] + bi1;
                float g0 = 0.5f * v0 * (1.f + erff(v0 * 0.7071067811865476f));
                float g1 = 0.5f * v1 * (1.f + erff(v1 * 0.7071067811865476f));
                __nv_bfloat162 hh = __floats2bfloat162_rn(g0, g1);
                float l0 = g0 - __bfloat162float(__low2bfloat16(hh));
                float l1 = g1 - __bfloat162float(__high2bfloat16(hh));
                __nv_bfloat162 ll = __floats2bfloat162_rn(l0, l1);
                size_t o = ((size_t)row * DFF + col) * 2;
                *(uint32_t*)((char*)g_hhi + o) = *(uint32_t*)&hh;
                *(uint32_t*)((char*)g_hlo + o) = *(uint32_t*)&ll;
            }
        }
    }
    #undef STAGE
}

__global__ void __launch_bounds__(256, 1) k_gemm2_mma(const float* __restrict__ b2) {
    extern __shared__ __align__(128) char smem[];
    const int tid = threadIdx.x, wid = tid >> 5, lane = tid & 31;
    const int g = lane >> 2, t4 = lane & 3;
    const int row0 = blockIdx.y * BM;
    if (row0 >= g_total) return;
    int e = 0;
    #pragma unroll
    for (int i = 1; i < E; i++) if (row0 >= g_off[i]) e = i;
    const int n0 = blockIdx.x * BN;
    const int wm = (wid & 1) * 64, wn = (wid >> 1) * 64;
    const uint32_t sb = smem_u32(smem);

    const int lq = lane & 7;
    uint32_t a_off[4], b_off[4];
    #pragma unroll
    for (int mt = 0; mt < 4; mt++)
        a_off[mt] = (uint32_t)((wm + mt*16 + lq + ((lane>>3)&1)*8)*ROWB + ((lane>>4)&1)*16);
    #pragma unroll
    for (int q = 0; q < 4; q++)
        b_off[q] = (uint32_t)(ABLK + (wn + q*16 + ((lane>>4)&1)*8 + lq)*ROWB + ((lane>>3)&1)*16);

    #define STAGE(st, c) do { \
        uint32_t base = sb + (st)*STGB; \
        int k0 = (c)*BK; \
        _Pragma("unroll") \
        for (int j = 0; j < 4; j++) { \
            int cid = j*256 + tid, row = cid >> 3, grp = cid & 7; \
            const char* src = (grp < 4 ? (const char*)g_hhi : (const char*)g_hlo) \
                              + ((size_t)(row0 + row)*DFF + k0)*2 + (grp & 3)*16; \
            CPA(base + row*ROWB + grp*16, src); \
        } \
        _Pragma("unroll") \
        for (int j = 0; j < 8; j++) { \
            int cid = j*256 + tid, row = cid >> 3, grp = cid & 7; \
            const char* src = (grp < 4 ? (const char*)g_w2hi : (const char*)g_w2lo) \
                              + (((size_t)e*D + n0 + row)*DFF + k0)*2 + (grp & 3)*16; \
            CPA(base + ABLK + row*ROWB + grp*16, src); \
        } \
    } while (0)

    const int NC = DFF / BK;   // 128
    #pragma unroll
    for (int c = 0; c < STAGES-1; c++) { STAGE(c, c); CPCOMMIT(); }

    float acc[4][8][4] = {};
    for (int c = 0; c < NC; c++) {
        CPWAIT(STAGES-2);
        __syncthreads();
        if (c + STAGES-1 < NC) STAGE((c + STAGES-1) & (STAGES-1), c + STAGES-1);
        CPCOMMIT();
        const uint32_t sbase = sb + (c & (STAGES-1)) * STGB;
        #pragma unroll
        for (int ks = 0; ks < 2; ks++) {
            uint32_t ah[4][4], al[4][4];
            #pragma unroll
            for (int mt = 0; mt < 4; mt++) {
                LDSM4(ah[mt], sbase + a_off[mt] + ks*32);
                LDSM4(al[mt], sbase + a_off[mt] + ks*32 + 64);
            }
            #pragma unroll
            for (int h = 0; h < 2; h++) {
                uint32_t bhq[2][4], blq[2][4];
                #pragma unroll
                for (int qq = 0; qq < 2; qq++) {
                    int q = h*2 + qq;
                    LDSM4(bhq[qq], sbase + b_off[q] + ks*32);
                    LDSM4(blq[qq], sbase + b_off[q] + ks*32 + 64);
                }
                #pragma unroll
                for (int mt = 0; mt < 4; mt++)
                    #pragma unroll
                    for (int nt = 0; nt < 4; nt++) {
                        uint32_t* bh = &bhq[nt>>1][(nt&1)*2];
                        uint32_t* bl = &blq[nt>>1][(nt&1)*2];
                        MMA(acc[mt][h*4+nt], ah[mt], bh);
                        MMA(acc[mt][h*4+nt], ah[mt], bl);
                        MMA(acc[mt][h*4+nt], al[mt], bh);
                    }
            }
        }
    }

    #pragma unroll
    for (int mt = 0; mt < 4; mt++) {
        #pragma unroll
        for (int nt = 0; nt < 8; nt++) {
            int col = n0 + wn + nt*8 + t4*2;
            float bi0 = __ldg(&b2[e*D + col]);
            float bi1 = __ldg(&b2[e*D + col + 1]);
            #pragma unroll
            for (int h = 0; h < 2; h++) {
                int row = row0 + wm + mt*16 + g + h*8;
                float2 v = make_float2(acc[mt][nt][2*h] + bi0, acc[mt][nt][2*h+1] + bi1);
                *(float2*)(g_y + (size_t)row * D + col) = v;
            }
        }
    }
    #undef STAGE
}

// ---------------- combine ----------------
__global__ void k_combine(float* __restrict__ out) {
    int i = blockIdx.x*blockDim.x + threadIdx.x;
    if (i >= TOK*D) return;
    int t = i >> 10;
    int d = i & 1023;
    int s0 = g_slot_of[t*2], s1 = g_slot_of[t*2+1];
    out[i] = g_gw[t*2]   * g_y[(size_t)s0*D + d]
           + g_gw[t*2+1] * g_y[(size_t)s1*D + d];
}

// ---------------- launch ----------------
extern "C" void kernel_launch(void* const* d_in, const int* in_sizes, int n_in,
                              void* d_out, int out_size) {
    const float* x  = (const float*)d_in[0];
    const float* Wg = (const float*)d_in[1];
    const float* W1 = (const float*)d_in[2];
    const float* b1 = (const float*)d_in[3];
    const float* W2 = (const float*)d_in[4];
    const float* b2 = (const float*)d_in[5];
    float* out = (float*)d_out;

    cudaFuncSetAttribute(k_gemm1_mma, cudaFuncAttributeMaxDynamicSharedMemorySize, SMEM_BYTES);
    cudaFuncSetAttribute(k_gemm2_mma, cudaFuncAttributeMaxDynamicSharedMemorySize, SMEM_BYTES);

    k_init<<<(MAXROWS + 255)/256, 256>>>();
    k_gate<<<TOK/8, 256>>>(x, Wg);
    k_offsets<<<1,1>>>(out + (size_t)TOK*D, (out_size > TOK*D) ? 1 : 0);
    k_scatter<<<(TOK*2 + 255)/256, 256>>>();
    k_split_x<<<(TOK*D/4 + 255)/256, 256>>>(x);
    k_tsplit<<<dim3(DFF/32, D/32, E), dim3(32,8)>>>(W1, D, DFF, 0);
    k_tsplit<<<dim3(D/32, DFF/32, E), dim3(32,8)>>>(W2, DFF, D, 1);
    k_gemm1_mma<<<dim3(DFF/BN, NROWT), 256, SMEM_BYTES>>>(b1);
    k_gemm2_mma<<<dim3(D/BN, NROWT), 256, SMEM_BYTES>>>(b2);
    k_combine<<<(TOK*D + 255)/256, 256>>>(out);
}

// round 8
// speedup vs baseline: 4.7866x; 2.0769x over previous
#include <cuda_runtime.h>
#include <cuda_fp16.h>
#include <math.h>
#include <stdint.h>

#define D    1024
#define DFF  4096
#define E    8
#define TOK  8192
#define BM   128             // CTA rows
#define BN   256             // CTA cols
#define BK   32              // fp16 per K chunk
#define STAGES 4
#define ROWB 80              // 64B data + 16B pad
#define ABLK (BM*ROWB)       // 10240
#define BBLK (BN*ROWB)       // 20480
#define STGB (ABLK+BBLK)     // 30720
#define SMEM_BYTES (STAGES*STGB)   // 122880
#define MAXROWS (2*TOK + E*BM)     // 17408
#define NROWT (MAXROWS/BM)         // 136

// ---------------- scratch ----------------
__device__ int   g_eid[TOK*2];
__device__ float g_gw[TOK*2];
__device__ int   g_counts[E];
__device__ int   g_off[E+1];
__device__ int   g_cursor[E];
__device__ int   g_total;
__device__ int   g_slot_token[MAXROWS];
__device__ int   g_slot_of[TOK*2];
__device__ float g_usage[E];
__device__ __half g_xh[TOK*D];
__device__ __half g_w1h[E*DFF*D];              // [E][DFF][D] (transposed)
__device__ __half g_w2h[E*D*DFF];              // [E][D][DFF] (transposed)
__device__ __half g_hh[(size_t)MAXROWS*DFF];   // fp16 h between GEMMs
__device__ float  g_y[(size_t)MAXROWS*D];

// ---------------- helpers ----------------
__device__ __forceinline__ uint32_t smem_u32(const void* p) {
    uint32_t a;
    asm("{ .reg .u64 t; cvta.to.shared.u64 t, %1; cvt.u32.u64 %0, t; }" : "=r"(a) : "l"(p));
    return a;
}
#define CPA(dst, src) asm volatile("cp.async.cg.shared.global [%0], [%1], 16;" :: "r"(dst), "l"(src) : "memory")
#define CPCOMMIT()    asm volatile("cp.async.commit_group;" ::: "memory")
#define CPWAIT(n)     asm volatile("cp.async.wait_group %0;" :: "n"(n) : "memory")
#define MMA(c, a, b) asm volatile( \
    "mma.sync.aligned.m16n8k16.row.col.f32.f16.f16.f32 " \
    "{%0,%1,%2,%3},{%4,%5,%6,%7},{%8,%9},{%0,%1,%2,%3};" \
    : "+f"((c)[0]),"+f"((c)[1]),"+f"((c)[2]),"+f"((c)[3]) \
    : "r"((a)[0]),"r"((a)[1]),"r"((a)[2]),"r"((a)[3]),"r"((b)[0]),"r"((b)[1]))
#define LDSM4(r, a) asm volatile( \
    "ldmatrix.sync.aligned.m8n8.x4.shared.b16 {%0,%1,%2,%3}, [%4];" \
    : "=r"((r)[0]),"=r"((r)[1]),"=r"((r)[2]),"=r"((r)[3]) : "r"(a))

// ---------------- init ----------------
__global__ void k_init() {
    int i = blockIdx.x*blockDim.x + threadIdx.x;
    if (i < MAXROWS) g_slot_token[i] = 0;
    if (i < E) { g_counts[i] = 0; g_usage[i] = 0.f; }
}

// ---------------- gating ----------------
__global__ __launch_bounds__(256) void k_gate(const float* __restrict__ x,
                                              const float* __restrict__ Wg) {
    __shared__ float sWg[E*D];
    for (int i = threadIdx.x; i < E*D; i += blockDim.x) sWg[i] = Wg[i];
    __syncthreads();
    int warp = threadIdx.x >> 5, lane = threadIdx.x & 31;
    int t = blockIdx.x * 8 + warp;
    if (t >= TOK) return;
    const float* xr = x + (size_t)t * D;
    float acc[E];
    #pragma unroll
    for (int e = 0; e < E; e++) acc[e] = 0.f;
    for (int d = lane; d < D; d += 32) {
        float xv = xr[d];
        #pragma unroll
        for (int e = 0; e < E; e++) acc[e] += xv * sWg[e*D + d];
    }
    #pragma unroll
    for (int e = 0; e < E; e++)
        #pragma unroll
        for (int o = 16; o > 0; o >>= 1)
            acc[e] += __shfl_xor_sync(0xffffffffu, acc[e], o);
    if (lane == 0) {
        int i0 = 0; float v0 = acc[0];
        #pragma unroll
        for (int e = 1; e < E; e++) if (acc[e] > v0) { v0 = acc[e]; i0 = e; }
        int i1 = -1; float v1 = -INFINITY;
        #pragma unroll
        for (int e = 0; e < E; e++) if (e != i0 && acc[e] > v1) { v1 = acc[e]; i1 = e; }
        float ex = expf(v1 - v0);
        float inv = 1.f / (1.f + ex);
        g_eid[t*2] = i0; g_eid[t*2+1] = i1;
        g_gw[t*2]  = inv; g_gw[t*2+1] = ex * inv;
        atomicAdd(&g_counts[i0], 1); atomicAdd(&g_counts[i1], 1);
        atomicAdd(&g_usage[i0], inv); atomicAdd(&g_usage[i1], ex*inv);
    }
}

// ---------------- offsets + lb loss ----------------
__global__ void k_offsets(float* loss_out, int write_loss) {
    int off = 0;
    g_off[0] = 0;
    for (int e = 0; e < E; e++) {
        g_cursor[e] = off;
        off += (g_counts[e] + BM - 1) / BM * BM;
        g_off[e+1] = off;
    }
    g_total = off;
    if (write_loss) {
        float u[E]; float mean = 0.f;
        for (int e = 0; e < E; e++) { u[e] = g_usage[e] / (float)TOK; mean += u[e]; }
        mean /= (float)E;
        float var = 0.f;
        for (int e = 0; e < E; e++) { float d = u[e] - mean; var += d * d; }
        var /= (float)(E - 1);
        loss_out[0] = var * 0.01f;
    }
}

// ---------------- scatter ----------------
__global__ void k_scatter() {
    int i = blockIdx.x*blockDim.x + threadIdx.x;
    if (i >= TOK*2) return;
    int e = g_eid[i];
    int pos = atomicAdd(&g_cursor[e], 1);
    g_slot_token[pos] = i >> 1;
    g_slot_of[i] = pos;
}

// ---------------- x -> fp16 ----------------
__global__ void k_half_x(const float* __restrict__ x) {
    int i = (blockIdx.x*blockDim.x + threadIdx.x) * 4;
    if (i >= TOK*D) return;
    float4 v = *(const float4*)(x + i);
    __half2 a = __floats2half2_rn(v.x, v.y);
    __half2 b = __floats2half2_rn(v.z, v.w);
    *(uint2*)((char*)g_xh + (size_t)i*2) = make_uint2(*(uint32_t*)&a, *(uint32_t*)&b);
}

// ---------------- transpose + fp16 weights ----------------
// in: [E][R][C] fp32 -> out: [E][C][R] fp16. which: 0->W1, 1->W2
__global__ void k_thalf(const float* __restrict__ W, int R, int C, int which) {
    __shared__ float t[32][33];
    int e = blockIdx.z;
    int c0 = blockIdx.x * 32, r0 = blockIdx.y * 32;
    int tx = threadIdx.x, ty = threadIdx.y;
    const float* in = W + (size_t)e * R * C;
    #pragma unroll
    for (int i = ty; i < 32; i += 8)
        t[i][tx] = in[(size_t)(r0 + i) * C + c0 + tx];
    __syncthreads();
    __half* oh = which ? g_w2h : g_w1h;
    size_t ob = (size_t)e * C * R;
    #pragma unroll
    for (int i = ty; i < 32; i += 8)
        oh[ob + (size_t)(c0 + i) * R + r0 + tx] = __float2half_rn(t[tx][i]);
}

// ================= fp16 mma.sync GEMMs: 128x256 CTA, 64x64 warp tile, ldmatrix =================
// stage: [A 128 rows x 80B][B 256 rows x 80B]; row = 64B fp16 data + 16B pad

__global__ void __launch_bounds__(256, 1) k_gemm1_mma(const float* __restrict__ b1) {
    extern __shared__ __align__(128) char smem[];
    __shared__ int stok[BM];
    const int tid = threadIdx.x, wid = tid >> 5, lane = tid & 31;
    const int g = lane >> 2, t4 = lane & 3;
    const int row0 = blockIdx.y * BM;
    if (row0 >= g_total) return;
    int e = 0;
    #pragma unroll
    for (int i = 1; i < E; i++) if (row0 >= g_off[i]) e = i;
    const int n0 = blockIdx.x * BN;
    const int wm = (wid & 1) * 64, wn = (wid >> 1) * 64;

    if (tid < BM) stok[tid] = g_slot_token[row0 + tid];
    __syncthreads();
    const uint32_t sb = smem_u32(smem);

    const int lq = lane & 7;
    uint32_t a_off[4], b_off[4];
    #pragma unroll
    for (int mt = 0; mt < 4; mt++)
        a_off[mt] = (uint32_t)((wm + mt*16 + lq + ((lane>>3)&1)*8)*ROWB + ((lane>>4)&1)*16);
    #pragma unroll
    for (int q = 0; q < 4; q++)
        b_off[q] = (uint32_t)(ABLK + (wn + q*16 + ((lane>>4)&1)*8 + lq)*ROWB + ((lane>>3)&1)*16);

    #define STAGE(st, c) do { \
        uint32_t base = sb + (st)*STGB; \
        int k0 = (c)*BK; \
        _Pragma("unroll") \
        for (int j = 0; j < 2; j++) { \
            int cid = j*256 + tid, row = cid >> 2, grp = cid & 3; \
            CPA(base + row*ROWB + grp*16, \
                (const char*)g_xh + ((size_t)stok[row]*D + k0)*2 + grp*16); \
        } \
        _Pragma("unroll") \
        for (int j = 0; j < 4; j++) { \
            int cid = j*256 + tid, row = cid >> 2, grp = cid & 3; \
            CPA(base + ABLK + row*ROWB + grp*16, \
                (const char*)g_w1h + (((size_t)e*DFF + n0 + row)*D + k0)*2 + grp*16); \
        } \
    } while (0)

    const int NC = D / BK;   // 32
    #pragma unroll
    for (int c = 0; c < STAGES-1; c++) { STAGE(c, c); CPCOMMIT(); }

    float acc[4][8][4] = {};
    for (int c = 0; c < NC; c++) {
        CPWAIT(STAGES-2);
        __syncthreads();
        if (c + STAGES-1 < NC) STAGE((c + STAGES-1) & (STAGES-1), c + STAGES-1);
        CPCOMMIT();
        const uint32_t sbase = sb + (c & (STAGES-1)) * STGB;
        #pragma unroll
        for (int ks = 0; ks < 2; ks++) {
            uint32_t a[4][4], bq[4][4];
            #pragma unroll
            for (int mt = 0; mt < 4; mt++) LDSM4(a[mt], sbase + a_off[mt] + ks*32);
            #pragma unroll
            for (int q = 0; q < 4; q++)    LDSM4(bq[q], sbase + b_off[q] + ks*32);
            #pragma unroll
            for (int mt = 0; mt < 4; mt++)
                #pragma unroll
                for (int nt = 0; nt < 8; nt++)
                    MMA(acc[mt][nt], a[mt], &bq[nt>>1][(nt&1)*2]);
        }
    }

    // epilogue: bias + exact gelu -> fp16 h
    #pragma unroll
    for (int mt = 0; mt < 4; mt++) {
        #pragma unroll
        for (int nt = 0; nt < 8; nt++) {
            int col = n0 + wn + nt*8 + t4*2;
            float bi0 = __ldg(&b1[e*DFF + col]);
            float bi1 = __ldg(&b1[e*DFF + col + 1]);
            #pragma unroll
            for (int h = 0; h < 2; h++) {
                int row = row0 + wm + mt*16 + g + h*8;
                float v0 = acc[mt][nt][2*h]   + bi0;
                float v1 = acc[mt][nt][2*h+1] + bi1;
                float g0 = 0.5f * v0 * (1.f + erff(v0 * 0.7071067811865476f));
                float g1 = 0.5f * v1 * (1.f + erff(v1 * 0.7071067811865476f));
                __half2 hv = __floats2half2_rn(g0, g1);
                *(uint32_t*)((char*)g_hh + ((size_t)row * DFF + col) * 2) = *(uint32_t*)&hv;
            }
        }
    }
    #undef STAGE
}

__global__ void __launch_bounds__(256, 1) k_gemm2_mma(const float* __restrict__ b2) {
    extern __shared__ __align__(128) char smem[];
    const int tid = threadIdx.x, wid = tid >> 5, lane = tid & 31;
    const int g = lane >> 2, t4 = lane & 3;
    const int row0 = blockIdx.y * BM;
    if (row0 >= g_total) return;
    int e = 0;
    #pragma unroll
    for (int i = 1; i < E; i++) if (row0 >= g_off[i]) e = i;
    const int n0 = blockIdx.x * BN;
    const int wm = (wid & 1) * 64, wn = (wid >> 1) * 64;
    const uint32_t sb = smem_u32(smem);

    const int lq = lane & 7;
    uint32_t a_off[4], b_off[4];
    #pragma unroll
    for (int mt = 0; mt < 4; mt++)
        a_off[mt] = (uint32_t)((wm + mt*16 + lq + ((lane>>3)&1)*8)*ROWB + ((lane>>4)&1)*16);
    #pragma unroll
    for (int q = 0; q < 4; q++)
        b_off[q] = (uint32_t)(ABLK + (wn + q*16 + ((lane>>4)&1)*8 + lq)*ROWB + ((lane>>3)&1)*16);

    #define STAGE(st, c) do { \
        uint32_t base = sb + (st)*STGB; \
        int k0 = (c)*BK; \
        _Pragma("unroll") \
        for (int j = 0; j < 2; j++) { \
            int cid = j*256 + tid, row = cid >> 2, grp = cid & 3; \
            CPA(base + row*ROWB + grp*16, \
                (const char*)g_hh + ((size_t)(row0 + row)*DFF + k0)*2 + grp*16); \
        } \
        _Pragma("unroll") \
        for (int j = 0; j < 4; j++) { \
            int cid = j*256 + tid, row = cid >> 2, grp = cid & 3; \
            CPA(base + ABLK + row*ROWB + grp*16, \
                (const char*)g_w2h + (((size_t)e*D + n0 + row)*DFF + k0)*2 + grp*16); \
        } \
    } while (0)

    const int NC = DFF / BK;   // 128
    #pragma unroll
    for (int c = 0; c < STAGES-1; c++) { STAGE(c, c); CPCOMMIT(); }

    float acc[4][8][4] = {};
    for (int c = 0; c < NC; c++) {
        CPWAIT(STAGES-2);
        __syncthreads();
        if (c + STAGES-1 < NC) STAGE((c + STAGES-1) & (STAGES-1), c + STAGES-1);
        CPCOMMIT();
        const uint32_t sbase = sb + (c & (STAGES-1)) * STGB;
        #pragma unroll
        for (int ks = 0; ks < 2; ks++) {
            uint32_t a[4][4], bq[4][4];
            #pragma unroll
            for (int mt = 0; mt < 4; mt++) LDSM4(a[mt], sbase + a_off[mt] + ks*32);
            #pragma unroll
            for (int q = 0; q < 4; q++)    LDSM4(bq[q], sbase + b_off[q] + ks*32);
            #pragma unroll
            for (int mt = 0; mt < 4; mt++)
                #pragma unroll
                for (int nt = 0; nt < 8; nt++)
                    MMA(acc[mt][nt], a[mt], &bq[nt>>1][(nt&1)*2]);
        }
    }

    #pragma unroll
    for (int mt = 0; mt < 4; mt++) {
        #pragma unroll
        for (int nt = 0; nt < 8; nt++) {
            int col = n0 + wn + nt*8 + t4*2;
            float bi0 = __ldg(&b2[e*D + col]);
            float bi1 = __ldg(&b2[e*D + col + 1]);
            #pragma unroll
            for (int h = 0; h < 2; h++) {
                int row = row0 + wm + mt*16 + g + h*8;
                float2 v = make_float2(acc[mt][nt][2*h] + bi0, acc[mt][nt][2*h+1] + bi1);
                *(float2*)(g_y + (size_t)row * D + col) = v;
            }
        }
    }
    #undef STAGE
}

// ---------------- combine ----------------
__global__ void k_combine(float* __restrict__ out) {
    int i = blockIdx.x*blockDim.x + threadIdx.x;
    if (i >= TOK*D) return;
    int t = i >> 10;
    int d = i & 1023;
    int s0 = g_slot_of[t*2], s1 = g_slot_of[t*2+1];
    out[i] = g_gw[t*2]   * g_y[(size_t)s0*D + d]
           + g_gw[t*2+1] * g_y[(size_t)s1*D + d];
}

// ---------------- launch ----------------
extern "C" void kernel_launch(void* const* d_in, const int* in_sizes, int n_in,
                              void* d_out, int out_size) {
    const float* x  = (const float*)d_in[0];
    const float* Wg = (const float*)d_in[1];
    const float* W1 = (const float*)d_in[2];
    const float* b1 = (const float*)d_in[3];
    const float* W2 = (const float*)d_in[4];
    const float* b2 = (const float*)d_in[5];
    float* out = (float*)d_out;

    cudaFuncSetAttribute(k_gemm1_mma, cudaFuncAttributeMaxDynamicSharedMemorySize, SMEM_BYTES);
    cudaFuncSetAttribute(k_gemm2_mma, cudaFuncAttributeMaxDynamicSharedMemorySize, SMEM_BYTES);

    k_init<<<(MAXROWS + 255)/256, 256>>>();
    k_gate<<<TOK/8, 256>>>(x, Wg);
    k_offsets<<<1,1>>>(out + (size_t)TOK*D, (out_size > TOK*D) ? 1 : 0);
    k_scatter<<<(TOK*2 + 255)/256, 256>>>();
    k_half_x<<<(TOK*D/4 + 255)/256, 256>>>(x);
    k_thalf<<<dim3(DFF/32, D/32, E), dim3(32,8)>>>(W1, D, DFF, 0);
    k_thalf<<<dim3(D/32, DFF/32, E), dim3(32,8)>>>(W2, DFF, D, 1);
    k_gemm1_mma<<<dim3(DFF/BN, NROWT), 256, SMEM_BYTES>>>(b1);
    k_gemm2_mma<<<dim3(D/BN, NROWT), 256, SMEM_BYTES>>>(b2);
    k_combine<<<(TOK*D + 255)/256, 256>>>(out);
}

// round 9
// speedup vs baseline: 5.3911x; 1.1263x over previous
#include <cuda_runtime.h>
#include <cuda_fp16.h>
#include <math.h>
#include <stdint.h>

#define D    1024
#define DFF  4096
#define E    8
#define TOK  8192
#define BM   128             // CTA rows
#define BN   256             // CTA cols
#define BK   64              // fp16 per K chunk (128B per row)
#define STAGES 3
#define ROWB 144             // 128B data + 16B pad
#define ABLK (BM*ROWB)       // 18432
#define BBLK (BN*ROWB)       // 36864
#define STGB (ABLK+BBLK)     // 55296
#define SMEM_BYTES (STAGES*STGB)   // 165888
#define MAXROWS (2*TOK + E*BM)     // 17408
#define NROWT (MAXROWS/BM)         // 136

// ---------------- scratch ----------------
__device__ int   g_eid[TOK*2];
__device__ float g_gw[TOK*2];
__device__ int   g_counts[E];
__device__ int   g_off[E+1];
__device__ int   g_cursor[E];
__device__ int   g_total;
__device__ int   g_slot_token[MAXROWS];
__device__ int   g_slot_of[TOK*2];
__device__ float g_usage[E];
__device__ __half g_xh[TOK*D];
__device__ __half g_w1h[E*DFF*D];              // [E][DFF][D] (transposed)
__device__ __half g_w2h[E*D*DFF];              // [E][D][DFF] (transposed)
__device__ __half g_hh[(size_t)MAXROWS*DFF];   // fp16 h between GEMMs
__device__ float  g_y[(size_t)MAXROWS*D];

// ---------------- helpers ----------------
__device__ __forceinline__ uint32_t smem_u32(const void* p) {
    uint32_t a;
    asm("{ .reg .u64 t; cvta.to.shared.u64 t, %1; cvt.u32.u64 %0, t; }" : "=r"(a) : "l"(p));
    return a;
}
#define CPA(dst, src) asm volatile("cp.async.cg.shared.global [%0], [%1], 16;" :: "r"(dst), "l"(src) : "memory")
#define CPCOMMIT()    asm volatile("cp.async.commit_group;" ::: "memory")
#define CPWAIT(n)     asm volatile("cp.async.wait_group %0;" :: "n"(n) : "memory")
#define MMA(c, a, b) asm volatile( \
    "mma.sync.aligned.m16n8k16.row.col.f32.f16.f16.f32 " \
    "{%0,%1,%2,%3},{%4,%5,%6,%7},{%8,%9},{%0,%1,%2,%3};" \
    : "+f"((c)[0]),"+f"((c)[1]),"+f"((c)[2]),"+f"((c)[3]) \
    : "r"((a)[0]),"r"((a)[1]),"r"((a)[2]),"r"((a)[3]),"r"((b)[0]),"r"((b)[1]))
#define LDSM4(r, a) asm volatile( \
    "ldmatrix.sync.aligned.m8n8.x4.shared.b16 {%0,%1,%2,%3}, [%4];" \
    : "=r"((r)[0]),"=r"((r)[1]),"=r"((r)[2]),"=r"((r)[3]) : "r"(a))

// ---------------- init ----------------
__global__ void k_init() {
    int i = blockIdx.x*blockDim.x + threadIdx.x;
    if (i < MAXROWS) g_slot_token[i] = 0;
    if (i < E) { g_counts[i] = 0; g_usage[i] = 0.f; }
}

// ---------------- gating (+ fused x->fp16) ----------------
__global__ __launch_bounds__(256) void k_gate(const float* __restrict__ x,
                                              const float* __restrict__ Wg) {
    __shared__ float sWg[E*D];
    for (int i = threadIdx.x; i < E*D; i += blockDim.x) sWg[i] = Wg[i];
    __syncthreads();
    int warp = threadIdx.x >> 5, lane = threadIdx.x & 31;
    int t = blockIdx.x * 8 + warp;
    if (t >= TOK) return;
    const float* xr = x + (size_t)t * D;
    __half* xo = g_xh + (size_t)t * D;
    float acc[E];
    #pragma unroll
    for (int e = 0; e < E; e++) acc[e] = 0.f;
    for (int d = lane; d < D; d += 32) {
        float xv = xr[d];
        xo[d] = __float2half_rn(xv);
        #pragma unroll
        for (int e = 0; e < E; e++) acc[e] += xv * sWg[e*D + d];
    }
    #pragma unroll
    for (int e = 0; e < E; e++)
        #pragma unroll
        for (int o = 16; o > 0; o >>= 1)
            acc[e] += __shfl_xor_sync(0xffffffffu, acc[e], o);
    if (lane == 0) {
        int i0 = 0; float v0 = acc[0];
        #pragma unroll
        for (int e = 1; e < E; e++) if (acc[e] > v0) { v0 = acc[e]; i0 = e; }
        int i1 = -1; float v1 = -INFINITY;
        #pragma unroll
        for (int e = 0; e < E; e++) if (e != i0 && acc[e] > v1) { v1 = acc[e]; i1 = e; }
        float ex = expf(v1 - v0);
        float inv = 1.f / (1.f + ex);
        g_eid[t*2] = i0; g_eid[t*2+1] = i1;
        g_gw[t*2]  = inv; g_gw[t*2+1] = ex * inv;
        atomicAdd(&g_counts[i0], 1); atomicAdd(&g_counts[i1], 1);
        atomicAdd(&g_usage[i0], inv); atomicAdd(&g_usage[i1], ex*inv);
    }
}

// ---------------- offsets + lb loss ----------------
__global__ void k_offsets(float* loss_out, int write_loss) {
    int off = 0;
    g_off[0] = 0;
    for (int e = 0; e < E; e++) {
        g_cursor[e] = off;
        off += (g_counts[e] + BM - 1) / BM * BM;
        g_off[e+1] = off;
    }
    g_total = off;
    if (write_loss) {
        float u[E]; float mean = 0.f;
        for (int e = 0; e < E; e++) { u[e] = g_usage[e] / (float)TOK; mean += u[e]; }
        mean /= (float)E;
        float var = 0.f;
        for (int e = 0; e < E; e++) { float d = u[e] - mean; var += d * d; }
        var /= (float)(E - 1);
        loss_out[0] = var * 0.01f;
    }
}

// ---------------- scatter ----------------
__global__ void k_scatter() {
    int i = blockIdx.x*blockDim.x + threadIdx.x;
    if (i >= TOK*2) return;
    int e = g_eid[i];
    int pos = atomicAdd(&g_cursor[e], 1);
    g_slot_token[pos] = i >> 1;
    g_slot_of[i] = pos;
}

// ---------------- transpose + fp16 weights ----------------
__global__ void k_thalf(const float* __restrict__ W, int R, int C, int which) {
    __shared__ float t[32][33];
    int e = blockIdx.z;
    int c0 = blockIdx.x * 32, r0 = blockIdx.y * 32;
    int tx = threadIdx.x, ty = threadIdx.y;
    const float* in = W + (size_t)e * R * C;
    #pragma unroll
    for (int i = ty; i < 32; i += 8)
        t[i][tx] = in[(size_t)(r0 + i) * C + c0 + tx];
    __syncthreads();
    __half* oh = which ? g_w2h : g_w1h;
    size_t ob = (size_t)e * C * R;
    #pragma unroll
    for (int i = ty; i < 32; i += 8)
        oh[ob + (size_t)(c0 + i) * R + r0 + tx] = __float2half_rn(t[tx][i]);
}

// ================= fp16 mma.sync GEMMs: 128x256 CTA, 64x64 warp tile, BK=64 =================
// stage: [A 128 rows x 144B][B 256 rows x 144B]; row = 128B fp16 data + 16B pad

__global__ void __launch_bounds__(256, 1) k_gemm1_mma(const float* __restrict__ b1) {
    extern __shared__ __align__(128) char smem[];
    __shared__ int stok[BM];
    const int tid = threadIdx.x, wid = tid >> 5, lane = tid & 31;
    const int g = lane >> 2, t4 = lane & 3;
    const int row0 = blockIdx.y * BM;
    if (row0 >= g_total) return;
    int e = 0;
    #pragma unroll
    for (int i = 1; i < E; i++) if (row0 >= g_off[i]) e = i;
    const int n0 = blockIdx.x * BN;
    const int wm = (wid & 1) * 64, wn = (wid >> 1) * 64;

    if (tid < BM) stok[tid] = g_slot_token[row0 + tid];
    __syncthreads();
    const uint32_t sb = smem_u32(smem);

    const int lq = lane & 7;
    uint32_t a_off[4], b_off[4];
    #pragma unroll
    for (int mt = 0; mt < 4; mt++)
        a_off[mt] = (uint32_t)((wm + mt*16 + lq + ((lane>>3)&1)*8)*ROWB + ((lane>>4)&1)*16);
    #pragma unroll
    for (int q = 0; q < 4; q++)
        b_off[q] = (uint32_t)(ABLK + (wn + q*16 + ((lane>>4)&1)*8 + lq)*ROWB + ((lane>>3)&1)*16);

    #define STAGE(st, c) do { \
        uint32_t base = sb + (st)*STGB; \
        int k0 = (c)*BK; \
        _Pragma("unroll") \
        for (int j = 0; j < 4; j++) { \
            int cid = j*256 + tid, row = cid >> 3, grp = cid & 7; \
            CPA(base + row*ROWB + grp*16, \
                (const char*)g_xh + ((size_t)stok[row]*D + k0)*2 + grp*16); \
        } \
        _Pragma("unroll") \
        for (int j = 0; j < 8; j++) { \
            int cid = j*256 + tid, row = cid >> 3, grp = cid & 7; \
            CPA(base + ABLK + row*ROWB + grp*16, \
                (const char*)g_w1h + (((size_t)e*DFF + n0 + row)*D + k0)*2 + grp*16); \
        } \
    } while (0)

    const int NC = D / BK;   // 16
    #pragma unroll
    for (int c = 0; c < STAGES-1; c++) { STAGE(c, c); CPCOMMIT(); }

    float acc[4][8][4] = {};
    int cs = 0, ls = STAGES-1;
    for (int c = 0; c < NC; c++) {
        CPWAIT(STAGES-2);
        __syncthreads();
        if (c + STAGES-1 < NC) STAGE(ls, c + STAGES-1);
        CPCOMMIT();
        const uint32_t sbase = sb + cs * STGB;
        #pragma unroll
        for (int ks = 0; ks < 4; ks++) {
            uint32_t a[4][4], bq[4][4];
            #pragma unroll
            for (int mt = 0; mt < 4; mt++) LDSM4(a[mt], sbase + a_off[mt] + ks*32);
            #pragma unroll
            for (int q = 0; q < 4; q++)    LDSM4(bq[q], sbase + b_off[q] + ks*32);
            #pragma unroll
            for (int mt = 0; mt < 4; mt++)
                #pragma unroll
                for (int nt = 0; nt < 8; nt++)
                    MMA(acc[mt][nt], a[mt], &bq[nt>>1][(nt&1)*2]);
        }
        cs = (cs == STAGES-1) ? 0 : cs + 1;
        ls = (ls == STAGES-1) ? 0 : ls + 1;
    }

    // epilogue: bias + exact gelu -> fp16 h
    #pragma unroll
    for (int mt = 0; mt < 4; mt++) {
        #pragma unroll
        for (int nt = 0; nt < 8; nt++) {
            int col = n0 + wn + nt*8 + t4*2;
            float bi0 = __ldg(&b1[e*DFF + col]);
            float bi1 = __ldg(&b1[e*DFF + col + 1]);
            #pragma unroll
            for (int h = 0; h < 2; h++) {
                int row = row0 + wm + mt*16 + g + h*8;
                float v0 = acc[mt][nt][2*h]   + bi0;
                float v1 = acc[mt][nt][2*h+1] + bi1;
                float g0 = 0.5f * v0 * (1.f + erff(v0 * 0.7071067811865476f));
                float g1 = 0.5f * v1 * (1.f + erff(v1 * 0.7071067811865476f));
                __half2 hv = __floats2half2_rn(g0, g1);
                *(uint32_t*)((char*)g_hh + ((size_t)row * DFF + col) * 2) = *(uint32_t*)&hv;
            }
        }
    }
    #undef STAGE
}

__global__ void __launch_bounds__(256, 1) k_gemm2_mma(const float* __restrict__ b2) {
    extern __shared__ __align__(128) char smem[];
    const int tid = threadIdx.x, wid = tid >> 5, lane = tid & 31;
    const int g = lane >> 2, t4 = lane & 3;
    const int row0 = blockIdx.y * BM;
    if (row0 >= g_total) return;
    int e = 0;
    #pragma unroll
    for (int i = 1; i < E; i++) if (row0 >= g_off[i]) e = i;
    const int n0 = blockIdx.x * BN;
    const int wm = (wid & 1) * 64, wn = (wid >> 1) * 64;
    const uint32_t sb = smem_u32(smem);

    const int lq = lane & 7;
    uint32_t a_off[4], b_off[4];
    #pragma unroll
    for (int mt = 0; mt < 4; mt++)
        a_off[mt] = (uint32_t)((wm + mt*16 + lq + ((lane>>3)&1)*8)*ROWB + ((lane>>4)&1)*16);
    #pragma unroll
    for (int q = 0; q < 4; q++)
        b_off[q] = (uint32_t)(ABLK + (wn + q*16 + ((lane>>4)&1)*8 + lq)*ROWB + ((lane>>3)&1)*16);

    #define STAGE(st, c) do { \
        uint32_t base = sb + (st)*STGB; \
        int k0 = (c)*BK; \
        _Pragma("unroll") \
        for (int j = 0; j < 4; j++) { \
            int cid = j*256 + tid, row = cid >> 3, grp = cid & 7; \
            CPA(base + row*ROWB + grp*16, \
                (const char*)g_hh + ((size_t)(row0 + row)*DFF + k0)*2 + grp*16); \
        } \
        _Pragma("unroll") \
        for (int j = 0; j < 8; j++) { \
            int cid = j*256 + tid, row = cid >> 3, grp = cid & 7; \
            CPA(base + ABLK + row*ROWB + grp*16, \
                (const char*)g_w2h + (((size_t)e*D + n0 + row)*DFF + k0)*2 + grp*16); \
        } \
    } while (0)

    const int NC = DFF / BK;   // 64
    #pragma unroll
    for (int c = 0; c < STAGES-1; c++) { STAGE(c, c); CPCOMMIT(); }

    float acc[4][8][4] = {};
    int cs = 0, ls = STAGES-1;
    for (int c = 0; c < NC; c++) {
        CPWAIT(STAGES-2);
        __syncthreads();
        if (c + STAGES-1 < NC) STAGE(ls, c + STAGES-1);
        CPCOMMIT();
        const uint32_t sbase = sb + cs * STGB;
        #pragma unroll
        for (int ks = 0; ks < 4; ks++) {
            uint32_t a[4][4], bq[4][4];
            #pragma unroll
            for (int mt = 0; mt < 4; mt++) LDSM4(a[mt], sbase + a_off[mt] + ks*32);
            #pragma unroll
            for (int q = 0; q < 4; q++)    LDSM4(bq[q], sbase + b_off[q] + ks*32);
            #pragma unroll
            for (int mt = 0; mt < 4; mt++)
                #pragma unroll
                for (int nt = 0; nt < 8; nt++)
                    MMA(acc[mt][nt], a[mt], &bq[nt>>1][(nt&1)*2]);
        }
        cs = (cs == STAGES-1) ? 0 : cs + 1;
        ls = (ls == STAGES-1) ? 0 : ls + 1;
    }

    #pragma unroll
    for (int mt = 0; mt < 4; mt++) {
        #pragma unroll
        for (int nt = 0; nt < 8; nt++) {
            int col = n0 + wn + nt*8 + t4*2;
            float bi0 = __ldg(&b2[e*D + col]);
            float bi1 = __ldg(&b2[e*D + col + 1]);
            #pragma unroll
            for (int h = 0; h < 2; h++) {
                int row = row0 + wm + mt*16 + g + h*8;
                float2 v = make_float2(acc[mt][nt][2*h] + bi0, acc[mt][nt][2*h+1] + bi1);
                *(float2*)(g_y + (size_t)row * D + col) = v;
            }
        }
    }
    #undef STAGE
}

// ---------------- combine ----------------
__global__ void k_combine(float* __restrict__ out) {
    int i = blockIdx.x*blockDim.x + threadIdx.x;
    if (i >= TOK*D) return;
    int t = i >> 10;
    int d = i & 1023;
    int s0 = g_slot_of[t*2], s1 = g_slot_of[t*2+1];
    out[i] = g_gw[t*2]   * g_y[(size_t)s0*D + d]
           + g_gw[t*2+1] * g_y[(size_t)s1*D + d];
}

// ---------------- launch ----------------
extern "C" void kernel_launch(void* const* d_in, const int* in_sizes, int n_in,
                              void* d_out, int out_size) {
    const float* x  = (const float*)d_in[0];
    const float* Wg = (const float*)d_in[1];
    const float* W1 = (const float*)d_in[2];
    const float* b1 = (const float*)d_in[3];
    const float* W2 = (const float*)d_in[4];
    const float* b2 = (const float*)d_in[5];
    float* out = (float*)d_out;

    cudaFuncSetAttribute(k_gemm1_mma, cudaFuncAttributeMaxDynamicSharedMemorySize, SMEM_BYTES);
    cudaFuncSetAttribute(k_gemm2_mma, cudaFuncAttributeMaxDynamicSharedMemorySize, SMEM_BYTES);

    k_init<<<(MAXROWS + 255)/256, 256>>>();
    k_gate<<<TOK/8, 256>>>(x, Wg);
    k_offsets<<<1,1>>>(out + (size_t)TOK*D, (out_size > TOK*D) ? 1 : 0);
    k_scatter<<<(TOK*2 + 255)/256, 256>>>();
    k_thalf<<<dim3(DFF/32, D/32, E), dim3(32,8)>>>(W1, D, DFF, 0);
    k_thalf<<<dim3(D/32, DFF/32, E), dim3(32,8)>>>(W2, DFF, D, 1);
    k_gemm1_mma<<<dim3(DFF/BN, NROWT), 256, SMEM_BYTES>>>(b1);
    k_gemm2_mma<<<dim3(D/BN, NROWT), 256, SMEM_BYTES>>>(b2);
    k_combine<<<(TOK*D + 255)/256, 256>>>(out);
}

// round 10
// speedup vs baseline: 5.3982x; 1.0013x over previous
#include <cuda_runtime.h>
#include <cuda_fp16.h>
#include <math.h>
#include <stdint.h>

#define D    1024
#define DFF  4096
#define E    8
#define TOK  8192
#define BM   128             // CTA rows
#define BN   256             // CTA cols
#define BK   64              // fp16 per K chunk (128B per row)
#define NT   512             // threads per CTA (16 warps)
#define STAGES 3
#define ROWB 144             // 128B data + 16B pad
#define ABLK (BM*ROWB)       // 18432
#define BBLK (BN*ROWB)       // 36864
#define STGB (ABLK+BBLK)     // 55296
#define SMEM_BYTES (STAGES*STGB)   // 165888
#define MAXROWS (2*TOK + E*BM)     // 17408
#define NROWT (MAXROWS/BM)         // 136

// ---------------- scratch ----------------
__device__ int   g_eid[TOK*2];
__device__ float g_gw[TOK*2];
__device__ int   g_counts[E];
__device__ int   g_off[E+1];
__device__ int   g_cursor[E];
__device__ int   g_total;
__device__ int   g_slot_token[MAXROWS];
__device__ int   g_slot_of[TOK*2];
__device__ float g_usage[E];
__device__ __half g_xh[TOK*D];
__device__ __half g_w1h[E*DFF*D];              // [E][DFF][D] (transposed)
__device__ __half g_w2h[E*D*DFF];              // [E][D][DFF] (transposed)
__device__ __half g_hh[(size_t)MAXROWS*DFF];   // fp16 h between GEMMs
__device__ float  g_y[(size_t)MAXROWS*D];

// ---------------- helpers ----------------
__device__ __forceinline__ uint32_t smem_u32(const void* p) {
    uint32_t a;
    asm("{ .reg .u64 t; cvta.to.shared.u64 t, %1; cvt.u32.u64 %0, t; }" : "=r"(a) : "l"(p));
    return a;
}
#define CPA(dst, src) asm volatile("cp.async.cg.shared.global [%0], [%1], 16;" :: "r"(dst), "l"(src) : "memory")
#define CPCOMMIT()    asm volatile("cp.async.commit_group;" ::: "memory")
#define CPWAIT(n)     asm volatile("cp.async.wait_group %0;" :: "n"(n) : "memory")
#define MMA(c, a, b) asm volatile( \
    "mma.sync.aligned.m16n8k16.row.col.f32.f16.f16.f32 " \
    "{%0,%1,%2,%3},{%4,%5,%6,%7},{%8,%9},{%0,%1,%2,%3};" \
    : "+f"((c)[0]),"+f"((c)[1]),"+f"((c)[2]),"+f"((c)[3]) \
    : "r"((a)[0]),"r"((a)[1]),"r"((a)[2]),"r"((a)[3]),"r"((b)[0]),"r"((b)[1]))
#define LDSM4(r, a) asm volatile( \
    "ldmatrix.sync.aligned.m8n8.x4.shared.b16 {%0,%1,%2,%3}, [%4];" \
    : "=r"((r)[0]),"=r"((r)[1]),"=r"((r)[2]),"=r"((r)[3]) : "r"(a))

// ---------------- init ----------------
__global__ void k_init() {
    int i = blockIdx.x*blockDim.x + threadIdx.x;
    if (i < MAXROWS) g_slot_token[i] = 0;
    if (i < E) { g_counts[i] = 0; g_usage[i] = 0.f; }
}

// ---------------- gating (+ fused x->fp16) ----------------
__global__ __launch_bounds__(256) void k_gate(const float* __restrict__ x,
                                              const float* __restrict__ Wg) {
    __shared__ float sWg[E*D];
    for (int i = threadIdx.x; i < E*D; i += blockDim.x) sWg[i] = Wg[i];
    __syncthreads();
    int warp = threadIdx.x >> 5, lane = threadIdx.x & 31;
    int t = blockIdx.x * 8 + warp;
    if (t >= TOK) return;
    const float* xr = x + (size_t)t * D;
    __half* xo = g_xh + (size_t)t * D;
    float acc[E];
    #pragma unroll
    for (int e = 0; e < E; e++) acc[e] = 0.f;
    for (int d = lane; d < D; d += 32) {
        float xv = xr[d];
        xo[d] = __float2half_rn(xv);
        #pragma unroll
        for (int e = 0; e < E; e++) acc[e] += xv * sWg[e*D + d];
    }
    #pragma unroll
    for (int e = 0; e < E; e++)
        #pragma unroll
        for (int o = 16; o > 0; o >>= 1)
            acc[e] += __shfl_xor_sync(0xffffffffu, acc[e], o);
    if (lane == 0) {
        int i0 = 0; float v0 = acc[0];
        #pragma unroll
        for (int e = 1; e < E; e++) if (acc[e] > v0) { v0 = acc[e]; i0 = e; }
        int i1 = -1; float v1 = -INFINITY;
        #pragma unroll
        for (int e = 0; e < E; e++) if (e != i0 && acc[e] > v1) { v1 = acc[e]; i1 = e; }
        float ex = expf(v1 - v0);
        float inv = 1.f / (1.f + ex);
        g_eid[t*2] = i0; g_eid[t*2+1] = i1;
        g_gw[t*2]  = inv; g_gw[t*2+1] = ex * inv;
        atomicAdd(&g_counts[i0], 1); atomicAdd(&g_counts[i1], 1);
        atomicAdd(&g_usage[i0], inv); atomicAdd(&g_usage[i1], ex*inv);
    }
}

// ---------------- offsets + lb loss ----------------
__global__ void k_offsets(float* loss_out, int write_loss) {
    int off = 0;
    g_off[0] = 0;
    for (int e = 0; e < E; e++) {
        g_cursor[e] = off;
        off += (g_counts[e] + BM - 1) / BM * BM;
        g_off[e+1] = off;
    }
    g_total = off;
    if (write_loss) {
        float u[E]; float mean = 0.f;
        for (int e = 0; e < E; e++) { u[e] = g_usage[e] / (float)TOK; mean += u[e]; }
        mean /= (float)E;
        float var = 0.f;
        for (int e = 0; e < E; e++) { float d = u[e] - mean; var += d * d; }
        var /= (float)(E - 1);
        loss_out[0] = var * 0.01f;
    }
}

// ---------------- scatter ----------------
__global__ void k_scatter() {
    int i = blockIdx.x*blockDim.x + threadIdx.x;
    if (i >= TOK*2) return;
    int e = g_eid[i];
    int pos = atomicAdd(&g_cursor[e], 1);
    g_slot_token[pos] = i >> 1;
    g_slot_of[i] = pos;
}

// ---------------- transpose + fp16 weights ----------------
__global__ void k_thalf(const float* __restrict__ W, int R, int C, int which) {
    __shared__ float t[32][33];
    int e = blockIdx.z;
    int c0 = blockIdx.x * 32, r0 = blockIdx.y * 32;
    int tx = threadIdx.x, ty = threadIdx.y;
    const float* in = W + (size_t)e * R * C;
    #pragma unroll
    for (int i = ty; i < 32; i += 8)
        t[i][tx] = in[(size_t)(r0 + i) * C + c0 + tx];
    __syncthreads();
    __half* oh = which ? g_w2h : g_w1h;
    size_t ob = (size_t)e * C * R;
    #pragma unroll
    for (int i = ty; i < 32; i += 8)
        oh[ob + (size_t)(c0 + i) * R + r0 + tx] = __float2half_rn(t[tx][i]);
}

// ================= fp16 mma.sync GEMMs: 128x256 CTA, 512 threads, 64x32 warp tile =================
// stage: [A 128 rows x 144B][B 256 rows x 144B]; row = 128B fp16 data + 16B pad

__global__ void __launch_bounds__(NT, 1) k_gemm1_mma(const float* __restrict__ b1) {
    extern __shared__ __align__(128) char smem[];
    __shared__ int stok[BM];
    const int tid = threadIdx.x, wid = tid >> 5, lane = tid & 31;
    const int g = lane >> 2, t4 = lane & 3;
    const int row0 = blockIdx.y * BM;
    if (row0 >= g_total) return;
    int e = 0;
    #pragma unroll
    for (int i = 1; i < E; i++) if (row0 >= g_off[i]) e = i;
    const int n0 = blockIdx.x * BN;
    const int wm = (wid & 1) * 64, wn = (wid >> 1) * 32;

    if (tid < BM) stok[tid] = g_slot_token[row0 + tid];
    __syncthreads();
    const uint32_t sb = smem_u32(smem);

    const int lq = lane & 7;
    uint32_t a_off[4], b_off[2];
    #pragma unroll
    for (int mt = 0; mt < 4; mt++)
        a_off[mt] = (uint32_t)((wm + mt*16 + lq + ((lane>>3)&1)*8)*ROWB + ((lane>>4)&1)*16);
    #pragma unroll
    for (int q = 0; q < 2; q++)
        b_off[q] = (uint32_t)(ABLK + (wn + q*16 + ((lane>>4)&1)*8 + lq)*ROWB + ((lane>>3)&1)*16);

    #define STAGE(st, c) do { \
        uint32_t base = sb + (st)*STGB; \
        int k0 = (c)*BK; \
        _Pragma("unroll") \
        for (int j = 0; j < 2; j++) { \
            int cid = j*NT + tid, row = cid >> 3, grp = cid & 7; \
            CPA(base + row*ROWB + grp*16, \
                (const char*)g_xh + ((size_t)stok[row]*D + k0)*2 + grp*16); \
        } \
        _Pragma("unroll") \
        for (int j = 0; j < 4; j++) { \
            int cid = j*NT + tid, row = cid >> 3, grp = cid & 7; \
            CPA(base + ABLK + row*ROWB + grp*16, \
                (const char*)g_w1h + (((size_t)e*DFF + n0 + row)*D + k0)*2 + grp*16); \
        } \
    } while (0)

    const int NC = D / BK;   // 16
    #pragma unroll
    for (int c = 0; c < STAGES-1; c++) { STAGE(c, c); CPCOMMIT(); }

    float acc[4][4][4] = {};
    int cs = 0, ls = STAGES-1;
    for (int c = 0; c < NC; c++) {
        CPWAIT(STAGES-2);
        __syncthreads();
        if (c + STAGES-1 < NC) STAGE(ls, c + STAGES-1);
        CPCOMMIT();
        const uint32_t sbase = sb + cs * STGB;
        #pragma unroll
        for (int ks = 0; ks < 4; ks++) {
            uint32_t a[4][4], bq[2][4];
            #pragma unroll
            for (int mt = 0; mt < 4; mt++) LDSM4(a[mt], sbase + a_off[mt] + ks*32);
            #pragma unroll
            for (int q = 0; q < 2; q++)    LDSM4(bq[q], sbase + b_off[q] + ks*32);
            #pragma unroll
            for (int mt = 0; mt < 4; mt++)
                #pragma unroll
                for (int nt = 0; nt < 4; nt++)
                    MMA(acc[mt][nt], a[mt], &bq[nt>>1][(nt&1)*2]);
        }
        cs = (cs == STAGES-1) ? 0 : cs + 1;
        ls = (ls == STAGES-1) ? 0 : ls + 1;
    }

    // epilogue: bias + exact gelu -> fp16 h
    #pragma unroll
    for (int mt = 0; mt < 4; mt++) {
        #pragma unroll
        for (int nt = 0; nt < 4; nt++) {
            int col = n0 + wn + nt*8 + t4*2;
            float bi0 = __ldg(&b1[e*DFF + col]);
            float bi1 = __ldg(&b1[e*DFF + col + 1]);
            #pragma unroll
            for (int h = 0; h < 2; h++) {
                int row = row0 + wm + mt*16 + g + h*8;
                float v0 = acc[mt][nt][2*h]   + bi0;
                float v1 = acc[mt][nt][2*h+1] + bi1;
                float g0 = 0.5f * v0 * (1.f + erff(v0 * 0.7071067811865476f));
                float g1 = 0.5f * v1 * (1.f + erff(v1 * 0.7071067811865476f));
                __half2 hv = __floats2half2_rn(g0, g1);
                *(uint32_t*)((char*)g_hh + ((size_t)row * DFF + col) * 2) = *(uint32_t*)&hv;
            }
        }
    }
    #undef STAGE
}

__global__ void __launch_bounds__(NT, 1) k_gemm2_mma(const float* __restrict__ b2) {
    extern __shared__ __align__(128) char smem[];
    const int tid = threadIdx.x, wid = tid >> 5, lane = tid & 31;
    const int g = lane >> 2, t4 = lane & 3;
    const int row0 = blockIdx.y * BM;
    if (row0 >= g_total) return;
    int e = 0;
    #pragma unroll
    for (int i = 1; i < E; i++) if (row0 >= g_off[i]) e = i;
    const int n0 = blockIdx.x * BN;
    const int wm = (wid & 1) * 64, wn = (wid >> 1) * 32;
    const uint32_t sb = smem_u32(smem);

    const int lq = lane & 7;
    uint32_t a_off[4], b_off[2];
    #pragma unroll
    for (int mt = 0; mt < 4; mt++)
        a_off[mt] = (uint32_t)((wm + mt*16 + lq + ((lane>>3)&1)*8)*ROWB + ((lane>>4)&1)*16);
    #pragma unroll
    for (int q = 0; q < 2; q++)
        b_off[q] = (uint32_t)(ABLK + (wn + q*16 + ((lane>>4)&1)*8 + lq)*ROWB + ((lane>>3)&1)*16);

    #define STAGE(st, c) do { \
        uint32_t base = sb + (st)*STGB; \
        int k0 = (c)*BK; \
        _Pragma("unroll") \
        for (int j = 0; j < 2; j++) { \
            int cid = j*NT + tid, row = cid >> 3, grp = cid & 7; \
            CPA(base + row*ROWB + grp*16, \
                (const char*)g_hh + ((size_t)(row0 + row)*DFF + k0)*2 + grp*16); \
        } \
        _Pragma("unroll") \
        for (int j = 0; j < 4; j++) { \
            int cid = j*NT + tid, row = cid >> 3, grp = cid & 7; \
            CPA(base + ABLK + row*ROWB + grp*16, \
                (const char*)g_w2h + (((size_t)e*D + n0 + row)*DFF + k0)*2 + grp*16); \
        } \
    } while (0)

    const int NC = DFF / BK;   // 64
    #pragma unroll
    for (int c = 0; c < STAGES-1; c++) { STAGE(c, c); CPCOMMIT(); }

    float acc[4][4][4] = {};
    int cs = 0, ls = STAGES-1;
    for (int c = 0; c < NC; c++) {
        CPWAIT(STAGES-2);
        __syncthreads();
        if (c + STAGES-1 < NC) STAGE(ls, c + STAGES-1);
        CPCOMMIT();
        const uint32_t sbase = sb + cs * STGB;
        #pragma unroll
        for (int ks = 0; ks < 4; ks++) {
            uint32_t a[4][4], bq[2][4];
            #pragma unroll
            for (int mt = 0; mt < 4; mt++) LDSM4(a[mt], sbase + a_off[mt] + ks*32);
            #pragma unroll
            for (int q = 0; q < 2; q++)    LDSM4(bq[q], sbase + b_off[q] + ks*32);
            #pragma unroll
            for (int mt = 0; mt < 4; mt++)
                #pragma unroll
                for (int nt = 0; nt < 4; nt++)
                    MMA(acc[mt][nt], a[mt], &bq[nt>>1][(nt&1)*2]);
        }
        cs = (cs == STAGES-1) ? 0 : cs + 1;
        ls = (ls == STAGES-1) ? 0 : ls + 1;
    }

    #pragma unroll
    for (int mt = 0; mt < 4; mt++) {
        #pragma unroll
        for (int nt = 0; nt < 4; nt++) {
            int col = n0 + wn + nt*8 + t4*2;
            float bi0 = __ldg(&b2[e*D + col]);
            float bi1 = __ldg(&b2[e*D + col + 1]);
            #pragma unroll
            for (int h = 0; h < 2; h++) {
                int row = row0 + wm + mt*16 + g + h*8;
                float2 v = make_float2(acc[mt][nt][2*h] + bi0, acc[mt][nt][2*h+1] + bi1);
                *(float2*)(g_y + (size_t)row * D + col) = v;
            }
        }
    }
    #undef STAGE
}

// ---------------- combine ----------------
__global__ void k_combine(float* __restrict__ out) {
    int i = blockIdx.x*blockDim.x + threadIdx.x;
    if (i >= TOK*D) return;
    int t = i >> 10;
    int d = i & 1023;
    int s0 = g_slot_of[t*2], s1 = g_slot_of[t*2+1];
    out[i] = g_gw[t*2]   * g_y[(size_t)s0*D + d]
           + g_gw[t*2+1] * g_y[(size_t)s1*D + d];
}

// ---------------- launch ----------------
extern "C" void kernel_launch(void* const* d_in, const int* in_sizes, int n_in,
                              void* d_out, int out_size) {
    const float* x  = (const float*)d_in[0];
    const float* Wg = (const float*)d_in[1];
    const float* W1 = (const float*)d_in[2];
    const float* b1 = (const float*)d_in[3];
    const float* W2 = (const float*)d_in[4];
    const float* b2 = (const float*)d_in[5];
    float* out = (float*)d_out;

    cudaFuncSetAttribute(k_gemm1_mma, cudaFuncAttributeMaxDynamicSharedMemorySize, SMEM_BYTES);
    cudaFuncSetAttribute(k_gemm2_mma, cudaFuncAttributeMaxDynamicSharedMemorySize, SMEM_BYTES);

    k_init<<<(MAXROWS + 255)/256, 256>>>();
    k_gate<<<TOK/8, 256>>>(x, Wg);
    k_offsets<<<1,1>>>(out + (size_t)TOK*D, (out_size > TOK*D) ? 1 : 0);
    k_scatter<<<(TOK*2 + 255)/256, 256>>>();
    k_thalf<<<dim3(DFF/32, D/32, E), dim3(32,8)>>>(W1, D, DFF, 0);
    k_thalf<<<dim3(D/32, DFF/32, E), dim3(32,8)>>>(W2, DFF, D, 1);
    k_gemm1_mma<<<dim3(DFF/BN, NROWT), NT, SMEM_BYTES>>>(b1);
    k_gemm2_mma<<<dim3(D/BN, NROWT), NT, SMEM_BYTES>>>(b2);
    k_combine<<<(TOK*D + 255)/256, 256>>>(out);
}

// round 11
// speedup vs baseline: 6.3568x; 1.1776x over previous
#include <cuda_runtime.h>
#include <cuda_fp16.h>
#include <math.h>
#include <stdint.h>

#define D    1024
#define DFF  4096
#define E    8
#define TOK  8192
#define BM   128
#define BN   256
#define BK   64              // fp16 per K chunk (128B per row)
#define NT   512
#define STAGES 4
#define ASTG 16384           // A tile chunk bytes (128 x 128B)
#define BSTG 32768           // B tile chunk bytes (256 x 128B)
#define STGB (ASTG+BSTG)     // 49152
#define SMEM_BYTES (1024 + STAGES*STGB)   // 197632
#define MAXROWS (2*TOK + E*BM)     // 17408
#define NROWT (MAXROWS/BM)         // 136

// ---------------- scratch ----------------
__device__ int   g_eid[TOK*2];
__device__ float g_gw[TOK*2];
__device__ int   g_counts[E];
__device__ int   g_off[E+1];
__device__ int   g_cursor[E];
__device__ int   g_total;
__device__ int   g_slot_token[MAXROWS];
__device__ int   g_slot_of[TOK*2];
__device__ float g_usage[E];
// tile-chunk-contiguous, pre-swizzled operand buffers
__device__ uint8_t g_xa[(size_t)NROWT*16*ASTG];        // [tile][kc][16KB]  36MB
__device__ uint8_t g_w1t[(size_t)E*16*16*BSTG];        // [e][nb][kc][32KB] 64MB
__device__ uint8_t g_w2t[(size_t)E*4*64*BSTG];         // [e][nb][kc][32KB] 64MB
__device__ uint8_t g_ht[(size_t)NROWT*64*ASTG];        // [tile][kc][16KB] 143MB
__device__ float   g_y[(size_t)MAXROWS*D];

// ---------------- helpers ----------------
__device__ __forceinline__ uint32_t smem_u32(const void* p) {
    uint32_t a;
    asm("{ .reg .u64 t; cvta.to.shared.u64 t, %1; cvt.u32.u64 %0, t; }" : "=r"(a) : "l"(p));
    return a;
}
#define MBAR_INIT(a,c) asm volatile("mbarrier.init.shared.b64 [%0], %1;" :: "r"(a), "r"(c) : "memory")
#define MBAR_EXPECT(a,tx) asm volatile("mbarrier.arrive.expect_tx.shared.b64 _, [%0], %1;" :: "r"(a), "r"(tx) : "memory")
#define BULK(dst, src, sz, bar) asm volatile( \
    "cp.async.bulk.shared::cluster.global.mbarrier::complete_tx::bytes [%0], [%1], %2, [%3];" \
    :: "r"(dst), "l"(src), "r"(sz), "r"(bar) : "memory")
#define MBAR_WAIT(a,p) do { uint32_t _m=(a); uint32_t _p=(p); uint32_t _d; \
    asm volatile("{\n\t.reg .pred p;\n\tmbarrier.try_wait.parity.acquire.cta.shared::cta.b64 p, [%1], %2;\n\tselp.b32 %0,1,0,p;\n\t}" \
        : "=r"(_d) : "r"(_m), "r"(_p) : "memory"); \
    if (!_d) { asm volatile("{\n\t.reg .pred P1;\n\tWL%=:\n\tmbarrier.try_wait.parity.acquire.cta.shared::cta.b64 P1, [%0], %1, 0x989680;\n\t@P1 bra.uni WD%=;\n\tbra.uni WL%=;\n\tWD%=:\n\t}" \
        :: "r"(_m), "r"(_p) : "memory"); } } while(0)
#define MMA(c, a, b) asm volatile( \
    "mma.sync.aligned.m16n8k16.row.col.f32.f16.f16.f32 " \
    "{%0,%1,%2,%3},{%4,%5,%6,%7},{%8,%9},{%0,%1,%2,%3};" \
    : "+f"((c)[0]),"+f"((c)[1]),"+f"((c)[2]),"+f"((c)[3]) \
    : "r"((a)[0]),"r"((a)[1]),"r"((a)[2]),"r"((a)[3]),"r"((b)[0]),"r"((b)[1]))
#define LDSM4(r, a) asm volatile( \
    "ldmatrix.sync.aligned.m8n8.x4.shared.b16 {%0,%1,%2,%3}, [%4];" \
    : "=r"((r)[0]),"=r"((r)[1]),"=r"((r)[2]),"=r"((r)[3]) : "r"(a))

// ---------------- init ----------------
__global__ void k_init() {
    int i = blockIdx.x*blockDim.x + threadIdx.x;
    if (i < MAXROWS) g_slot_token[i] = 0;
    if (i < E) { g_counts[i] = 0; g_usage[i] = 0.f; }
}

// ---------------- gating ----------------
__global__ __launch_bounds__(256) void k_gate(const float* __restrict__ x,
                                              const float* __restrict__ Wg) {
    __shared__ float sWg[E*D];
    for (int i = threadIdx.x; i < E*D; i += blockDim.x) sWg[i] = Wg[i];
    __syncthreads();
    int warp = threadIdx.x >> 5, lane = threadIdx.x & 31;
    int t = blockIdx.x * 8 + warp;
    if (t >= TOK) return;
    const float* xr = x + (size_t)t * D;
    float acc[E];
    #pragma unroll
    for (int e = 0; e < E; e++) acc[e] = 0.f;
    for (int d = lane; d < D; d += 32) {
        float xv = xr[d];
        #pragma unroll
        for (int e = 0; e < E; e++) acc[e] += xv * sWg[e*D + d];
    }
    #pragma unroll
    for (int e = 0; e < E; e++)
        #pragma unroll
        for (int o = 16; o > 0; o >>= 1)
            acc[e] += __shfl_xor_sync(0xffffffffu, acc[e], o);
    if (lane == 0) {
        int i0 = 0; float v0 = acc[0];
        #pragma unroll
        for (int e = 1; e < E; e++) if (acc[e] > v0) { v0 = acc[e]; i0 = e; }
        int i1 = -1; float v1 = -INFINITY;
        #pragma unroll
        for (int e = 0; e < E; e++) if (e != i0 && acc[e] > v1) { v1 = acc[e]; i1 = e; }
        float ex = expf(v1 - v0);
        float inv = 1.f / (1.f + ex);
        g_eid[t*2] = i0; g_eid[t*2+1] = i1;
        g_gw[t*2]  = inv; g_gw[t*2+1] = ex * inv;
        atomicAdd(&g_counts[i0], 1); atomicAdd(&g_counts[i1], 1);
        atomicAdd(&g_usage[i0], inv); atomicAdd(&g_usage[i1], ex*inv);
    }
}

// ---------------- offsets + lb loss ----------------
__global__ void k_offsets(float* loss_out, int write_loss) {
    int off = 0;
    g_off[0] = 0;
    for (int e = 0; e < E; e++) {
        g_cursor[e] = off;
        off += (g_counts[e] + BM - 1) / BM * BM;
        g_off[e+1] = off;
    }
    g_total = off;
    if (write_loss) {
        float u[E]; float mean = 0.f;
        for (int e = 0; e < E; e++) { u[e] = g_usage[e] / (float)TOK; mean += u[e]; }
        mean /= (float)E;
        float var = 0.f;
        for (int e = 0; e < E; e++) { float d = u[e] - mean; var += d * d; }
        var /= (float)(E - 1);
        loss_out[0] = var * 0.01f;
    }
}

// ---------------- scatter ----------------
__global__ void k_scatter() {
    int i = blockIdx.x*blockDim.x + threadIdx.x;
    if (i >= TOK*2) return;
    int e = g_eid[i];
    int pos = atomicAdd(&g_cursor[e], 1);
    g_slot_token[pos] = i >> 1;
    g_slot_of[i] = pos;
}

// ---------------- prep A: gather + fp16 + tile-chunk swizzled layout ----------------
__global__ __launch_bounds__(256) void k_prep_a(const float* __restrict__ x) {
    int id = blockIdx.x*256 + threadIdx.x;     // NROWT*16*128*8 threads
    int gg = id & 7;
    int r  = (id >> 3) & 127;
    int c  = (id >> 10) & 15;
    int t  = id >> 14;
    if (t >= NROWT) return;
    int token = g_slot_token[t*128 + r];
    const float* src = x + (size_t)token*D + c*64 + gg*8;
    float4 v0 = *(const float4*)src;
    float4 v1 = *(const float4*)(src + 4);
    __half2 h0 = __floats2half2_rn(v0.x, v0.y);
    __half2 h1 = __floats2half2_rn(v0.z, v0.w);
    __half2 h2 = __floats2half2_rn(v1.x, v1.y);
    __half2 h3 = __floats2half2_rn(v1.z, v1.w);
    uint4 out = make_uint4(*(uint32_t*)&h0, *(uint32_t*)&h1, *(uint32_t*)&h2, *(uint32_t*)&h3);
    *(uint4*)(g_xa + ((size_t)(t*16 + c) << 14) + r*128 + ((gg ^ (r & 7)) << 4)) = out;
}

// ---------------- prep weights: transpose + fp16 + tiled swizzled layout ----------------
// in: [E][R][C] fp32 (R = k-dim, C = n-dim). out tiles: [e][nb][kc][256 x 128B swizzled]
__global__ void k_prep_w(const float* __restrict__ W, int R, int C, int which) {
    __shared__ float t[32][33];
    int e = blockIdx.z;
    int c0 = blockIdx.x * 32, r0 = blockIdx.y * 32;
    int tx = threadIdx.x, ty = threadIdx.y;
    const float* in = W + (size_t)e * R * C;
    #pragma unroll
    for (int i = ty; i < 32; i += 8)
        t[i][tx] = in[(size_t)(r0 + i) * C + c0 + tx];
    __syncthreads();
    uint8_t* outb = which ? g_w2t : g_w1t;
    int NBn = C >> 8, KCn = R >> 6;
    int k = r0 + tx;
    int kc = k >> 6, gg = (k & 63) >> 3, b7 = k & 7;
    #pragma unroll
    for (int i = ty; i < 32; i += 8) {
        int f = c0 + i;
        int n = f & 255, nb = f >> 8;
        __half hv = __float2half_rn(t[tx][i]);
        *(__half*)(outb + ((size_t)((e*NBn + nb)*KCn + kc) << 15)
                   + (n << 7) + ((gg ^ (n & 7)) << 4) + b7*2) = hv;
    }
}

// ================= bulk-copy fp16 GEMMs: 128x256 CTA, 512 thr, 64x32 warp tile =================

__global__ void __launch_bounds__(NT, 1) k_gemm1_mma(const float* __restrict__ b1) {
    extern __shared__ __align__(128) char smem[];
    const int tid = threadIdx.x, wid = tid >> 5, lane = tid & 31;
    const int g = lane >> 2, t4 = lane & 3;
    const int row0 = blockIdx.y * BM;
    if (row0 >= g_total) return;
    int e = 0;
    #pragma unroll
    for (int i = 1; i < E; i++) if (row0 >= g_off[i]) e = i;
    const int n0 = blockIdx.x * BN;
    const int wm = (wid & 1) * 64, wn = (wid >> 1) * 32;
    const uint32_t sb = smem_u32(smem);

    const uint8_t* Abase = g_xa + ((size_t)blockIdx.y << 18);                  // tile*16*16384
    const uint8_t* Bbase = g_w1t + ((size_t)(e*16 + blockIdx.x) << 19);        // *16*32768

    if (tid == 0) {
        #pragma unroll
        for (int s = 0; s < STAGES; s++) MBAR_INIT(sb + s*8, 1);
    }
    __syncthreads();
    if (tid == 0) {
        #pragma unroll
        for (int s = 0; s < STAGES; s++) {
            MBAR_EXPECT(sb + s*8, STGB);
            BULK(sb + 1024 + s*STGB,         Abase + (size_t)s*ASTG, ASTG, sb + s*8);
            BULK(sb + 1024 + s*STGB + ASTG,  Bbase + (size_t)s*BSTG, BSTG, sb + s*8);
        }
    }

    // ldmatrix lane geometry (row&7 == lq for all fragments)
    const int lq = lane & 7;
    const int hiA = (lane >> 4) & 1, hiB = (lane >> 3) & 1;
    uint32_t aRow[4], bRow[2];
    #pragma unroll
    for (int mt = 0; mt < 4; mt++)
        aRow[mt] = (uint32_t)((wm + mt*16 + lq + ((lane>>3)&1)*8) * 128);
    #pragma unroll
    for (int q = 0; q < 2; q++)
        bRow[q] = (uint32_t)(ASTG + (wn + q*16 + ((lane>>4)&1)*8 + lq) * 128);

    const int NC = D / BK;   // 16
    float acc[4][4][4] = {};
    uint32_t ph = 0;
    for (int c = 0; c < NC; c++) {
        int b = c & (STAGES-1);
        MBAR_WAIT(sb + b*8, (ph >> b) & 1);
        ph ^= 1u << b;
        const uint32_t sbase = sb + 1024 + b*STGB;
        #pragma unroll
        for (int ks = 0; ks < 4; ks++) {
            const uint32_t colA = (uint32_t)((((ks<<1)|hiA) ^ lq) << 4);
            const uint32_t colB = (uint32_t)((((ks<<1)|hiB) ^ lq) << 4);
            uint32_t a[4][4], bq[2][4];
            #pragma unroll
            for (int mt = 0; mt < 4; mt++) LDSM4(a[mt], sbase + aRow[mt] + colA);
            #pragma unroll
            for (int q = 0; q < 2; q++)    LDSM4(bq[q], sbase + bRow[q] + colB);
            #pragma unroll
            for (int mt = 0; mt < 4; mt++)
                #pragma unroll
                for (int nt = 0; nt < 4; nt++)
                    MMA(acc[mt][nt], a[mt], &bq[nt>>1][(nt&1)*2]);
        }
        __syncthreads();
        if (c + STAGES < NC && tid == 0) {
            MBAR_EXPECT(sb + b*8, STGB);
            BULK(sbase,        Abase + (size_t)(c+STAGES)*ASTG, ASTG, sb + b*8);
            BULK(sbase + ASTG, Bbase + (size_t)(c+STAGES)*BSTG, BSTG, sb + b*8);
        }
    }

    // epilogue: bias + exact gelu -> g_ht (tile-chunk swizzled fp16)
    uint8_t* hb = g_ht + ((size_t)blockIdx.y << 20);   // tile*64*16384
    #pragma unroll
    for (int mt = 0; mt < 4; mt++) {
        #pragma unroll
        for (int nt = 0; nt < 4; nt++) {
            int col = n0 + wn + nt*8 + t4*2;
            float bi0 = __ldg(&b1[e*DFF + col]);
            float bi1 = __ldg(&b1[e*DFF + col + 1]);
            int kc = col >> 6, kk = col & 63;
            int gg = kk >> 3, b7 = kk & 7;
            #pragma unroll
            for (int h = 0; h < 2; h++) {
                int r = wm + mt*16 + g + h*8;
                float v0 = acc[mt][nt][2*h]   + bi0;
                float v1 = acc[mt][nt][2*h+1] + bi1;
                float g0 = 0.5f * v0 * (1.f + erff(v0 * 0.7071067811865476f));
                float g1 = 0.5f * v1 * (1.f + erff(v1 * 0.7071067811865476f));
                __half2 hv = __floats2half2_rn(g0, g1);
                *(uint32_t*)(hb + ((size_t)kc << 14) + (r << 7)
                             + ((gg ^ (r & 7)) << 4) + b7*2) = *(uint32_t*)&hv;
            }
        }
    }
}

__global__ void __launch_bounds__(NT, 1) k_gemm2_mma(const float* __restrict__ b2) {
    extern __shared__ __align__(128) char smem[];
    const int tid = threadIdx.x, wid = tid >> 5, lane = tid & 31;
    const int g = lane >> 2, t4 = lane & 3;
    const int row0 = blockIdx.y * BM;
    if (row0 >= g_total) return;
    int e = 0;
    #pragma unroll
    for (int i = 1; i < E; i++) if (row0 >= g_off[i]) e = i;
    const int n0 = blockIdx.x * BN;
    const int wm = (wid & 1) * 64, wn = (wid >> 1) * 32;
    const uint32_t sb = smem_u32(smem);

    const uint8_t* Abase = g_ht + ((size_t)blockIdx.y << 20);                  // tile*64*16384
    const uint8_t* Bbase = g_w2t + ((size_t)(e*4 + blockIdx.x) * 64 << 15);    // *64*32768

    if (tid == 0) {
        #pragma unroll
        for (int s = 0; s < STAGES; s++) MBAR_INIT(sb + s*8, 1);
    }
    __syncthreads();
    if (tid == 0) {
        #pragma unroll
        for (int s = 0; s < STAGES; s++) {
            MBAR_EXPECT(sb + s*8, STGB);
            BULK(sb + 1024 + s*STGB,         Abase + (size_t)s*ASTG, ASTG, sb + s*8);
            BULK(sb + 1024 + s*STGB + ASTG,  Bbase + (size_t)s*BSTG, BSTG, sb + s*8);
        }
    }

    const int lq = lane & 7;
    const int hiA = (lane >> 4) & 1, hiB = (lane >> 3) & 1;
    uint32_t aRow[4], bRow[2];
    #pragma unroll
    for (int mt = 0; mt < 4; mt++)
        aRow[mt] = (uint32_t)((wm + mt*16 + lq + ((lane>>3)&1)*8) * 128);
    #pragma unroll
    for (int q = 0; q < 2; q++)
        bRow[q] = (uint32_t)(ASTG + (wn + q*16 + ((lane>>4)&1)*8 + lq) * 128);

    const int NC = DFF / BK;   // 64
    float acc[4][4][4] = {};
    uint32_t ph = 0;
    for (int c = 0; c < NC; c++) {
        int b = c & (STAGES-1);
        MBAR_WAIT(sb + b*8, (ph >> b) & 1);
        ph ^= 1u << b;
        const uint32_t sbase = sb + 1024 + b*STGB;
        #pragma unroll
        for (int ks = 0; ks < 4; ks++) {
            const uint32_t colA = (uint32_t)((((ks<<1)|hiA) ^ lq) << 4);
            const uint32_t colB = (uint32_t)((((ks<<1)|hiB) ^ lq) << 4);
            uint32_t a[4][4], bq[2][4];
            #pragma unroll
            for (int mt = 0; mt < 4; mt++) LDSM4(a[mt], sbase + aRow[mt] + colA);
            #pragma unroll
            for (int q = 0; q < 2; q++)    LDSM4(bq[q], sbase + bRow[q] + colB);
            #pragma unroll
            for (int mt = 0; mt < 4; mt++)
                #pragma unroll
                for (int nt = 0; nt < 4; nt++)
                    MMA(acc[mt][nt], a[mt], &bq[nt>>1][(nt&1)*2]);
        }
        __syncthreads();
        if (c + STAGES < NC && tid == 0) {
            MBAR_EXPECT(sb + b*8, STGB);
            BULK(sbase,        Abase + (size_t)(c+STAGES)*ASTG, ASTG, sb + b*8);
            BULK(sbase + ASTG, Bbase + (size_t)(c+STAGES)*BSTG, BSTG, sb + b*8);
        }
    }

    #pragma unroll
    for (int mt = 0; mt < 4; mt++) {
        #pragma unroll
        for (int nt = 0; nt < 4; nt++) {
            int col = n0 + wn + nt*8 + t4*2;
            float bi0 = __ldg(&b2[e*D + col]);
            float bi1 = __ldg(&b2[e*D + col + 1]);
            #pragma unroll
            for (int h = 0; h < 2; h++) {
                int row = row0 + wm + mt*16 + g + h*8;
                float2 v = make_float2(acc[mt][nt][2*h] + bi0, acc[mt][nt][2*h+1] + bi1);
                *(float2*)(g_y + (size_t)row * D + col) = v;
            }
        }
    }
}

// ---------------- combine ----------------
__global__ void k_combine(float* __restrict__ out) {
    int i = blockIdx.x*blockDim.x + threadIdx.x;
    if (i >= TOK*D) return;
    int t = i >> 10;
    int d = i & 1023;
    int s0 = g_slot_of[t*2], s1 = g_slot_of[t*2+1];
    out[i] = g_gw[t*2]   * g_y[(size_t)s0*D + d]
           + g_gw[t*2+1] * g_y[(size_t)s1*D + d];
}

// ---------------- launch ----------------
extern "C" void kernel_launch(void* const* d_in, const int* in_sizes, int n_in,
                              void* d_out, int out_size) {
    const float* x  = (const float*)d_in[0];
    const float* Wg = (const float*)d_in[1];
    const float* W1 = (const float*)d_in[2];
    const float* b1 = (const float*)d_in[3];
    const float* W2 = (const float*)d_in[4];
    const float* b2 = (const float*)d_in[5];
    float* out = (float*)d_out;

    cudaFuncSetAttribute(k_gemm1_mma, cudaFuncAttributeMaxDynamicSharedMemorySize, SMEM_BYTES);
    cudaFuncSetAttribute(k_gemm2_mma, cudaFuncAttributeMaxDynamicSharedMemorySize, SMEM_BYTES);

    k_init<<<(MAXROWS + 255)/256, 256>>>();
    k_gate<<<TOK/8, 256>>>(x, Wg);
    k_offsets<<<1,1>>>(out + (size_t)TOK*D, (out_size > TOK*D) ? 1 : 0);
    k_scatter<<<(TOK*2 + 255)/256, 256>>>();
    k_prep_a<<<(NROWT*16*128*8)/256, 256>>>(x);
    k_prep_w<<<dim3(DFF/32, D/32, E), dim3(32,8)>>>(W1, D, DFF, 0);
    k_prep_w<<<dim3(D/32, DFF/32, E), dim3(32,8)>>>(W2, DFF, D, 1);
    k_gemm1_mma<<<dim3(DFF/BN, NROWT), NT, SMEM_BYTES>>>(b1);
    k_gemm2_mma<<<dim3(D/BN, NROWT), NT, SMEM_BYTES>>>(b2);
    k_combine<<<(TOK*D + 255)/256, 256>>>(out);
}

// round 12
// speedup vs baseline: 6.8061x; 1.0707x over previous
#include <cuda_runtime.h>
#include <cuda_fp16.h>
#include <math.h>
#include <stdint.h>

#define D    1024
#define DFF  4096
#define E    8
#define TOK  8192
#define BM   128
#define BN   256
#define NT   512
#define STAGES 2
#define A2   32768           // A stage bytes (2 x 16KB kc chunks, contiguous)
#define B2   65536           // B stage bytes (2 x 32KB kc chunks, contiguous)
#define STGB (A2+B2)         // 98304
#define SMEM_BYTES (1024 + STAGES*STGB)   // 197632
#define MAXROWS (2*TOK + E*BM)     // 17408
#define NROWT (MAXROWS/BM)         // 136

// ---------------- scratch ----------------
__device__ int   g_eid[TOK*2];
__device__ float g_gw[TOK*2];
__device__ int   g_counts[E];
__device__ int   g_off[E+1];
__device__ int   g_cursor[E];
__device__ int   g_total;
__device__ int   g_slot_token[MAXROWS];
__device__ int   g_slot_of[TOK*2];
__device__ float g_usage[E];
// tile-chunk-contiguous, pre-swizzled operand buffers
__device__ uint8_t g_xa[(size_t)NROWT*16*16384];       // [tile][kc][16KB]  36MB
__device__ uint8_t g_w1t[(size_t)E*16*16*32768];       // [e][nb][kc][32KB] 64MB
__device__ uint8_t g_w2t[(size_t)E*4*64*32768];        // [e][nb][kc][32KB] 64MB
__device__ uint8_t g_ht[(size_t)NROWT*64*16384];       // [tile][kc][16KB] 143MB
__device__ float   g_y[(size_t)MAXROWS*D];

// ---------------- helpers ----------------
__device__ __forceinline__ uint32_t smem_u32(const void* p) {
    uint32_t a;
    asm("{ .reg .u64 t; cvta.to.shared.u64 t, %1; cvt.u32.u64 %0, t; }" : "=r"(a) : "l"(p));
    return a;
}
#define MBAR_INIT(a,c) asm volatile("mbarrier.init.shared.b64 [%0], %1;" :: "r"(a), "r"(c) : "memory")
#define MBAR_EXPECT(a,tx) asm volatile("mbarrier.arrive.expect_tx.shared.b64 _, [%0], %1;" :: "r"(a), "r"(tx) : "memory")
#define BULK(dst, src, sz, bar) asm volatile( \
    "cp.async.bulk.shared::cluster.global.mbarrier::complete_tx::bytes [%0], [%1], %2, [%3];" \
    :: "r"(dst), "l"(src), "r"(sz), "r"(bar) : "memory")
#define MBAR_WAIT(a,p) do { uint32_t _m=(a); uint32_t _p=(p); uint32_t _d; \
    asm volatile("{\n\t.reg .pred p;\n\tmbarrier.try_wait.parity.acquire.cta.shared::cta.b64 p, [%1], %2;\n\tselp.b32 %0,1,0,p;\n\t}" \
        : "=r"(_d) : "r"(_m), "r"(_p) : "memory"); \
    if (!_d) { asm volatile("{\n\t.reg .pred P1;\n\tWL%=:\n\tmbarrier.try_wait.parity.acquire.cta.shared::cta.b64 P1, [%0], %1, 0x989680;\n\t@P1 bra.uni WD%=;\n\tbra.uni WL%=;\n\tWD%=:\n\t}" \
        :: "r"(_m), "r"(_p) : "memory"); } } while(0)
#define MMA(c, a, b) asm volatile( \
    "mma.sync.aligned.m16n8k16.row.col.f32.f16.f16.f32 " \
    "{%0,%1,%2,%3},{%4,%5,%6,%7},{%8,%9},{%0,%1,%2,%3};" \
    : "+f"((c)[0]),"+f"((c)[1]),"+f"((c)[2]),"+f"((c)[3]) \
    : "r"((a)[0]),"r"((a)[1]),"r"((a)[2]),"r"((a)[3]),"r"((b)[0]),"r"((b)[1]))
#define LDSM4(r, a) asm volatile( \
    "ldmatrix.sync.aligned.m8n8.x4.shared.b16 {%0,%1,%2,%3}, [%4];" \
    : "=r"((r)[0]),"=r"((r)[1]),"=r"((r)[2]),"=r"((r)[3]) : "r"(a))

// ---------------- init ----------------
__global__ void k_init() {
    int i = blockIdx.x*blockDim.x + threadIdx.x;
    if (i < MAXROWS) g_slot_token[i] = 0;
    if (i < E) { g_counts[i] = 0; g_usage[i] = 0.f; }
}

// ---------------- gating ----------------
__global__ __launch_bounds__(256) void k_gate(const float* __restrict__ x,
                                              const float* __restrict__ Wg) {
    __shared__ float sWg[E*D];
    for (int i = threadIdx.x; i < E*D; i += blockDim.x) sWg[i] = Wg[i];
    __syncthreads();
    int warp = threadIdx.x >> 5, lane = threadIdx.x & 31;
    int t = blockIdx.x * 8 + warp;
    if (t >= TOK) return;
    const float* xr = x + (size_t)t * D;
    float acc[E];
    #pragma unroll
    for (int e = 0; e < E; e++) acc[e] = 0.f;
    for (int d = lane; d < D; d += 32) {
        float xv = xr[d];
        #pragma unroll
        for (int e = 0; e < E; e++) acc[e] += xv * sWg[e*D + d];
    }
    #pragma unroll
    for (int e = 0; e < E; e++)
        #pragma unroll
        for (int o = 16; o > 0; o >>= 1)
            acc[e] += __shfl_xor_sync(0xffffffffu, acc[e], o);
    if (lane == 0) {
        int i0 = 0; float v0 = acc[0];
        #pragma unroll
        for (int e = 1; e < E; e++) if (acc[e] > v0) { v0 = acc[e]; i0 = e; }
        int i1 = -1; float v1 = -INFINITY;
        #pragma unroll
        for (int e = 0; e < E; e++) if (e != i0 && acc[e] > v1) { v1 = acc[e]; i1 = e; }
        float ex = expf(v1 - v0);
        float inv = 1.f / (1.f + ex);
        g_eid[t*2] = i0; g_eid[t*2+1] = i1;
        g_gw[t*2]  = inv; g_gw[t*2+1] = ex * inv;
        atomicAdd(&g_counts[i0], 1); atomicAdd(&g_counts[i1], 1);
        atomicAdd(&g_usage[i0], inv); atomicAdd(&g_usage[i1], ex*inv);
    }
}

// ---------------- offsets + lb loss ----------------
__global__ void k_offsets(float* loss_out, int write_loss) {
    int off = 0;
    g_off[0] = 0;
    for (int e = 0; e < E; e++) {
        g_cursor[e] = off;
        off += (g_counts[e] + BM - 1) / BM * BM;
        g_off[e+1] = off;
    }
    g_total = off;
    if (write_loss) {
        float u[E]; float mean = 0.f;
        for (int e = 0; e < E; e++) { u[e] = g_usage[e] / (float)TOK; mean += u[e]; }
        mean /= (float)E;
        float var = 0.f;
        for (int e = 0; e < E; e++) { float d = u[e] - mean; var += d * d; }
        var /= (float)(E - 1);
        loss_out[0] = var * 0.01f;
    }
}

// ---------------- scatter ----------------
__global__ void k_scatter() {
    int i = blockIdx.x*blockDim.x + threadIdx.x;
    if (i >= TOK*2) return;
    int e = g_eid[i];
    int pos = atomicAdd(&g_cursor[e], 1);
    g_slot_token[pos] = i >> 1;
    g_slot_of[i] = pos;
}

// ---------------- prep A: gather + fp16 + tile-chunk swizzled layout ----------------
__global__ __launch_bounds__(256) void k_prep_a(const float* __restrict__ x) {
    int id = blockIdx.x*256 + threadIdx.x;     // NROWT*16*128*8 threads
    int gg = id & 7;
    int r  = (id >> 3) & 127;
    int c  = (id >> 10) & 15;
    int t  = id >> 14;
    if (t >= NROWT) return;
    int token = g_slot_token[t*128 + r];
    const float* src = x + (size_t)token*D + c*64 + gg*8;
    float4 v0 = *(const float4*)src;
    float4 v1 = *(const float4*)(src + 4);
    __half2 h0 = __floats2half2_rn(v0.x, v0.y);
    __half2 h1 = __floats2half2_rn(v0.z, v0.w);
    __half2 h2 = __floats2half2_rn(v1.x, v1.y);
    __half2 h3 = __floats2half2_rn(v1.z, v1.w);
    uint4 out = make_uint4(*(uint32_t*)&h0, *(uint32_t*)&h1, *(uint32_t*)&h2, *(uint32_t*)&h3);
    *(uint4*)(g_xa + ((size_t)(t*16 + c) << 14) + r*128 + ((gg ^ (r & 7)) << 4)) = out;
}

// ---------------- prep weights: transpose + fp16 + tiled swizzled layout ----------------
__global__ void k_prep_w(const float* __restrict__ W, int R, int C, int which) {
    __shared__ float t[32][33];
    int e = blockIdx.z;
    int c0 = blockIdx.x * 32, r0 = blockIdx.y * 32;
    int tx = threadIdx.x, ty = threadIdx.y;
    const float* in = W + (size_t)e * R * C;
    #pragma unroll
    for (int i = ty; i < 32; i += 8)
        t[i][tx] = in[(size_t)(r0 + i) * C + c0 + tx];
    __syncthreads();
    uint8_t* outb = which ? g_w2t : g_w1t;
    int NBn = C >> 8, KCn = R >> 6;
    int k = r0 + tx;
    int kc = k >> 6, gg = (k & 63) >> 3, b7 = k & 7;
    #pragma unroll
    for (int i = ty; i < 32; i += 8) {
        int f = c0 + i;
        int n = f & 255, nb = f >> 8;
        __half hv = __float2half_rn(t[tx][i]);
        *(__half*)(outb + ((size_t)((e*NBn + nb)*KCn + kc) << 15)
                   + (n << 7) + ((gg ^ (n & 7)) << 4) + b7*2) = hv;
    }
}

// ================= bulk-copy fp16 GEMMs: 128x256 CTA, 512 thr, BK=128 stages =================

__global__ void __launch_bounds__(NT, 1) k_gemm1_mma(const float* __restrict__ b1) {
    extern __shared__ __align__(128) char smem[];
    const int tid = threadIdx.x, wid = tid >> 5, lane = tid & 31;
    const int g = lane >> 2, t4 = lane & 3;
    const int row0 = blockIdx.y * BM;
    if (row0 >= g_total) return;
    int e = 0;
    #pragma unroll
    for (int i = 1; i < E; i++) if (row0 >= g_off[i]) e = i;
    const int n0 = blockIdx.x * BN;
    const int wm = (wid & 1) * 64, wn = (wid >> 1) * 32;
    const uint32_t sb = smem_u32(smem);

    const uint8_t* Abase = g_xa + ((size_t)blockIdx.y << 18);                  // tile*16*16384
    const uint8_t* Bbase = g_w1t + ((size_t)(e*16 + blockIdx.x) << 19);        // *16*32768

    if (tid == 0) {
        #pragma unroll
        for (int s = 0; s < STAGES; s++) MBAR_INIT(sb + s*8, 1);
    }
    __syncthreads();
    if (tid == 0) {
        #pragma unroll
        for (int s = 0; s < STAGES; s++) {
            MBAR_EXPECT(sb + s*8, STGB);
            BULK(sb + 1024 + s*STGB,      Abase + (size_t)s*A2, A2, sb + s*8);
            BULK(sb + 1024 + s*STGB + A2, Bbase + (size_t)s*B2, B2, sb + s*8);
        }
    }

    // ldmatrix lane geometry (row&7 == lq for all fragments)
    const int lq = lane & 7;
    const int hiA = (lane >> 4) & 1, hiB = (lane >> 3) & 1;
    uint32_t aRow[4], bRow[2];
    #pragma unroll
    for (int mt = 0; mt < 4; mt++)
        aRow[mt] = (uint32_t)((wm + mt*16 + lq + ((lane>>3)&1)*8) * 128);
    #pragma unroll
    for (int q = 0; q < 2; q++)
        bRow[q] = (uint32_t)(A2 + (wn + q*16 + ((lane>>4)&1)*8 + lq) * 128);

    const int NC = 8;   // D / 128
    float acc[4][4][4] = {};
    uint32_t ph = 0;
    for (int c = 0; c < NC; c++) {
        int b = c & 1;
        MBAR_WAIT(sb + b*8, (ph >> b) & 1);
        ph ^= 1u << b;
        const uint32_t sbase = sb + 1024 + b*STGB;
        #pragma unroll
        for (int hf = 0; hf < 2; hf++) {
            const uint32_t aSub = sbase + hf*16384;
            const uint32_t bSub = sbase + hf*32768;
            #pragma unroll
            for (int ks = 0; ks < 4; ks++) {
                const uint32_t colA = (uint32_t)((((ks<<1)|hiA) ^ lq) << 4);
                const uint32_t colB = (uint32_t)((((ks<<1)|hiB) ^ lq) << 4);
                uint32_t a[4][4], bq[2][4];
                #pragma unroll
                for (int mt = 0; mt < 4; mt++) LDSM4(a[mt], aSub + aRow[mt] + colA);
                #pragma unroll
                for (int q = 0; q < 2; q++)    LDSM4(bq[q], bSub + bRow[q] + colB);
                #pragma unroll
                for (int mt = 0; mt < 4; mt++)
                    #pragma unroll
                    for (int nt = 0; nt < 4; nt++)
                        MMA(acc[mt][nt], a[mt], &bq[nt>>1][(nt&1)*2]);
            }
        }
        __syncthreads();
        if (c + STAGES < NC && tid == 0) {
            MBAR_EXPECT(sb + b*8, STGB);
            BULK(sbase,      Abase + (size_t)(c+STAGES)*A2, A2, sb + b*8);
            BULK(sbase + A2, Bbase + (size_t)(c+STAGES)*B2, B2, sb + b*8);
        }
    }

    // epilogue: bias + exact gelu -> g_ht (tile-chunk swizzled fp16)
    uint8_t* hb = g_ht + ((size_t)blockIdx.y << 20);   // tile*64*16384
    #pragma unroll
    for (int mt = 0; mt < 4; mt++) {
        #pragma unroll
        for (int nt = 0; nt < 4; nt++) {
            int col = n0 + wn + nt*8 + t4*2;
            float bi0 = __ldg(&b1[e*DFF + col]);
            float bi1 = __ldg(&b1[e*DFF + col + 1]);
            int kc = col >> 6, kk = col & 63;
            int gg = kk >> 3, b7 = kk & 7;
            #pragma unroll
            for (int h = 0; h < 2; h++) {
                int r = wm + mt*16 + g + h*8;
                float v0 = acc[mt][nt][2*h]   + bi0;
                float v1 = acc[mt][nt][2*h+1] + bi1;
                float g0 = 0.5f * v0 * (1.f + erff(v0 * 0.7071067811865476f));
                float g1 = 0.5f * v1 * (1.f + erff(v1 * 0.7071067811865476f));
                __half2 hv = __floats2half2_rn(g0, g1);
                *(uint32_t*)(hb + ((size_t)kc << 14) + (r << 7)
                             + ((gg ^ (r & 7)) << 4) + b7*2) = *(uint32_t*)&hv;
            }
        }
    }
}

__global__ void __launch_bounds__(NT, 1) k_gemm2_mma(const float* __restrict__ b2) {
    extern __shared__ __align__(128) char smem[];
    const int tid = threadIdx.x, wid = tid >> 5, lane = tid & 31;
    const int g = lane >> 2, t4 = lane & 3;
    const int row0 = blockIdx.y * BM;
    if (row0 >= g_total) return;
    int e = 0;
    #pragma unroll
    for (int i = 1; i < E; i++) if (row0 >= g_off[i]) e = i;
    const int n0 = blockIdx.x * BN;
    const int wm = (wid & 1) * 64, wn = (wid >> 1) * 32;
    const uint32_t sb = smem_u32(smem);

    const uint8_t* Abase = g_ht + ((size_t)blockIdx.y << 20);                  // tile*64*16384
    const uint8_t* Bbase = g_w2t + ((size_t)(e*4 + blockIdx.x) * 64 << 15);    // *64*32768

    if (tid == 0) {
        #pragma unroll
        for (int s = 0; s < STAGES; s++) MBAR_INIT(sb + s*8, 1);
    }
    __syncthreads();
    if (tid == 0) {
        #pragma unroll
        for (int s = 0; s < STAGES; s++) {
            MBAR_EXPECT(sb + s*8, STGB);
            BULK(sb + 1024 + s*STGB,      Abase + (size_t)s*A2, A2, sb + s*8);
            BULK(sb + 1024 + s*STGB + A2, Bbase + (size_t)s*B2, B2, sb + s*8);
        }
    }

    const int lq = lane & 7;
    const int hiA = (lane >> 4) & 1, hiB = (lane >> 3) & 1;
    uint32_t aRow[4], bRow[2];
    #pragma unroll
    for (int mt = 0; mt < 4; mt++)
        aRow[mt] = (uint32_t)((wm + mt*16 + lq + ((lane>>3)&1)*8) * 128);
    #pragma unroll
    for (int q = 0; q < 2; q++)
        bRow[q] = (uint32_t)(A2 + (wn + q*16 + ((lane>>4)&1)*8 + lq) * 128);

    const int NC = 32;   // DFF / 128
    float acc[4][4][4] = {};
    uint32_t ph = 0;
    for (int c = 0; c < NC; c++) {
        int b = c & 1;
        MBAR_WAIT(sb + b*8, (ph >> b) & 1);
        ph ^= 1u << b;
        const uint32_t sbase = sb + 1024 + b*STGB;
        #pragma unroll
        for (int hf = 0; hf < 2; hf++) {
            const uint32_t aSub = sbase + hf*16384;
            const uint32_t bSub = sbase + hf*32768;
            #pragma unroll
            for (int ks = 0; ks < 4; ks++) {
                const uint32_t colA = (uint32_t)((((ks<<1)|hiA) ^ lq) << 4);
                const uint32_t colB = (uint32_t)((((ks<<1)|hiB) ^ lq) << 4);
                uint32_t a[4][4], bq[2][4];
                #pragma unroll
                for (int mt = 0; mt < 4; mt++) LDSM4(a[mt], aSub + aRow[mt] + colA);
                #pragma unroll
                for (int q = 0; q < 2; q++)    LDSM4(bq[q], bSub + bRow[q] + colB);
                #pragma unroll
                for (int mt = 0; mt < 4; mt++)
                    #pragma unroll
                    for (int nt = 0; nt < 4; nt++)
                        MMA(acc[mt][nt], a[mt], &bq[nt>>1][(nt&1)*2]);
            }
        }
        __syncthreads();
        if (c + STAGES < NC && tid == 0) {
            MBAR_EXPECT(sb + b*8, STGB);
            BULK(sbase,      Abase + (size_t)(c+STAGES)*A2, A2, sb + b*8);
            BULK(sbase + A2, Bbase + (size_t)(c+STAGES)*B2, B2, sb + b*8);
        }
    }

    #pragma unroll
    for (int mt = 0; mt < 4; mt++) {
        #pragma unroll
        for (int nt = 0; nt < 4; nt++) {
            int col = n0 + wn + nt*8 + t4*2;
            float bi0 = __ldg(&b2[e*D + col]);
            float bi1 = __ldg(&b2[e*D + col + 1]);
            #pragma unroll
            for (int h = 0; h < 2; h++) {
                int row = row0 + wm + mt*16 + g + h*8;
                float2 v = make_float2(acc[mt][nt][2*h] + bi0, acc[mt][nt][2*h+1] + bi1);
                *(float2*)(g_y + (size_t)row * D + col) = v;
            }
        }
    }
}

// ---------------- combine ----------------
__global__ void k_combine(float* __restrict__ out) {
    int i = blockIdx.x*blockDim.x + threadIdx.x;
    if (i >= TOK*D) return;
    int t = i >> 10;
    int d = i & 1023;
    int s0 = g_slot_of[t*2], s1 = g_slot_of[t*2+1];
    out[i] = g_gw[t*2]   * g_y[(size_t)s0*D + d]
           + g_gw[t*2+1] * g_y[(size_t)s1*D + d];
}

// ---------------- launch ----------------
extern "C" void kernel_launch(void* const* d_in, const int* in_sizes, int n_in,
                              void* d_out, int out_size) {
    const float* x  = (const float*)d_in[0];
    const float* Wg = (const float*)d_in[1];
    const float* W1 = (const float*)d_in[2];
    const float* b1 = (const float*)d_in[3];
    const float* W2 = (const float*)d_in[4];
    const float* b2 = (const float*)d_in[5];
    float* out = (float*)d_out;

    cudaFuncSetAttribute(k_gemm1_mma, cudaFuncAttributeMaxDynamicSharedMemorySize, SMEM_BYTES);
    cudaFuncSetAttribute(k_gemm2_mma, cudaFuncAttributeMaxDynamicSharedMemorySize, SMEM_BYTES);

    k_init<<<(MAXROWS + 255)/256, 256>>>();
    k_gate<<<TOK/8, 256>>>(x, Wg);
    k_offsets<<<1,1>>>(out + (size_t)TOK*D, (out_size > TOK*D) ? 1 : 0);
    k_scatter<<<(TOK*2 + 255)/256, 256>>>();
    k_prep_a<<<(NROWT*16*128*8)/256, 256>>>(x);
    k_prep_w<<<dim3(DFF/32, D/32, E), dim3(32,8)>>>(W1, D, DFF, 0);
    k_prep_w<<<dim3(D/32, DFF/32, E), dim3(32,8)>>>(W2, DFF, D, 1);
    k_gemm1_mma<<<dim3(DFF/BN, NROWT), NT, SMEM_BYTES>>>(b1);
    k_gemm2_mma<<<dim3(D/BN, NROWT), NT, SMEM_BYTES>>>(b2);
    k_combine<<<(TOK*D + 255)/256, 256>>>(out);
}